// round 5
// baseline (speedup 1.0000x reference)
#include <cuda_runtime.h>
#include <cuda_bf16.h>
#include <math.h>

#define N_POS   131072
#define KCODES  512
#define DDIM    64
#define MMA_BLOCKS 1024          // 128 positions per CTA
#define FB_THREADS_TOTAL 2048    // 4 CTAs x 512
#define TAU 2e-4f

// ---- device scratch (no allocation allowed) ----
__device__ int    g_counts[KCODES];
__device__ double g_sse[MMA_BLOCKS];
__device__ double g_fb_sse[FB_THREADS_TOTAL];
__device__ int    g_fb_list[N_POS];
__device__ int    g_fb_count;   // zero-init; finalize resets each run

// ---------- helpers ----------
static __device__ __forceinline__ unsigned long long pack2(float lo, float hi) {
    unsigned long long r;
    asm("mov.b64 %0, {%1, %2};" : "=l"(r) : "f"(lo), "f"(hi));
    return r;
}
static __device__ __forceinline__ float lo2(unsigned long long v) { return __uint_as_float((unsigned)v); }
static __device__ __forceinline__ float hi2(unsigned long long v) { return __uint_as_float((unsigned)(v >> 32)); }
static __device__ __forceinline__ unsigned long long ffma2(unsigned long long a, unsigned long long b, unsigned long long c) {
    unsigned long long d;
    asm("fma.rn.f32x2 %0, %1, %2, %3;" : "=l"(d) : "l"(a), "l"(b), "l"(c));
    return d;
}
static __device__ __forceinline__ unsigned long long fadd2(unsigned long long a, unsigned long long b) {
    unsigned long long d;
    asm("add.rn.f32x2 %0, %1, %2;" : "=l"(d) : "l"(a), "l"(b));
    return d;
}
static __device__ __forceinline__ void mma16816(float& c0, float& c1, float& c2, float& c3,
                                                unsigned a0, unsigned a1, unsigned a2, unsigned a3,
                                                unsigned b0, unsigned b1) {
    asm volatile("mma.sync.aligned.m16n8k16.row.col.f32.bf16.bf16.f32 "
                 "{%0,%1,%2,%3}, {%4,%5,%6,%7}, {%8,%9}, {%0,%1,%2,%3};"
                 : "+f"(c0), "+f"(c1), "+f"(c2), "+f"(c3)
                 : "r"(a0), "r"(a1), "r"(a2), "r"(a3), "r"(b0), "r"(b1));
}

// ---------- smem layout (bytes) for main kernel ----------
#define SE_H   0                        // e_hi bf16 [512][72]
#define SE_L   73728                    // e_lo
#define SZ_H   147456                   // z_hi bf16 [128][72]
#define SZ_L   165888
#define SEN    184320                   // float[512]
#define SZSQP  186368                   // float[512] partials
#define SZSQ   188416                   // float[128]
#define SBEST  188928                   // float[256]  (row*2 + nhalf)
#define SKIDX  189952                   // int[256]
#define SSEC   190976                   // float[256]
#define SHIST  192000                   // int[512]
#define SWSUM  194048                   // double[4]
#define MAIN_SMEM 194112

// ===========================================================================
// Main kernel: bf16 split-MMA filter + certainty test + epilogue
// 1024 CTAs x 512 threads; CTA covers 128 positions x all 512 codes
// ===========================================================================
__global__ __launch_bounds__(512, 1)
void vq_mma_kernel(const float* __restrict__ z, const float* __restrict__ e,
                   float* __restrict__ out) {
    extern __shared__ char sm[];
    __nv_bfloat16* sEh = (__nv_bfloat16*)(sm + SE_H);
    __nv_bfloat16* sEl = (__nv_bfloat16*)(sm + SE_L);
    __nv_bfloat16* sZh = (__nv_bfloat16*)(sm + SZ_H);
    __nv_bfloat16* sZl = (__nv_bfloat16*)(sm + SZ_L);
    float* sEN   = (float*)(sm + SEN);
    float* sZsqP = (float*)(sm + SZSQP);
    float* sZsq  = (float*)(sm + SZSQ);
    float* sBest = (float*)(sm + SBEST);
    int*   sK    = (int*)(sm + SKIDX);
    float* sSec  = (float*)(sm + SSEC);
    int*   sHist = (int*)(sm + SHIST);
    double* sW   = (double*)(sm + SWSUM);

    const int tid  = threadIdx.x;
    const int lane = tid & 31;
    const int w    = tid >> 5;
    const int p0   = blockIdx.x * 128;
    const int zbase = (p0 >> 12) * 262144 + (p0 & 4095);

    // ---- stage codebook: -2e as bf16 hi/lo (filter only), eN fp32 ----
    {
        const int n = tid;                       // 512 threads = 512 codes
        const float* row = e + n * DDIM;
        float s = 0.f;
        #pragma unroll 8
        for (int d = 0; d < DDIM; ++d) {
            float v = row[d];
            s = fmaf(v, v, s);
            float m = -2.f * v;
            __nv_bfloat16 h = __float2bfloat16_rn(m);
            __nv_bfloat16 l = __float2bfloat16_rn(m - __bfloat162float(h));
            sEh[n * 72 + d] = h;
            sEl[n * 72 + d] = l;
        }
        sEN[n]  = s;
        sHist[n] = 0;
    }
    // ---- stage z: bf16 hi/lo + zsq partials ----
    {
        const int row  = tid & 127;
        const int part = tid >> 7;               // 4 parts of 16 dims
        float s = 0.f;
        #pragma unroll
        for (int j = 0; j < 16; ++j) {
            int d = part * 16 + j;
            float v = __ldg(z + zbase + row + d * 4096);
            s = fmaf(v, v, s);
            __nv_bfloat16 h = __float2bfloat16_rn(v);
            __nv_bfloat16 l = __float2bfloat16_rn(v - __bfloat162float(h));
            sZh[row * 72 + d] = h;
            sZl[row * 72 + d] = l;
        }
        sZsqP[part * 128 + row] = s;
    }
    __syncthreads();
    if (tid < 128)
        sZsq[tid] = ((sZsqP[tid] + sZsqP[128 + tid]) + sZsqP[256 + tid]) + sZsqP[384 + tid];
    __syncthreads();

    // ---- MMA streaming ----
    const int mtile = w & 7;                     // 8 m-tiles of 16 rows
    const int nhalf = w >> 3;                    // 2 code halves of 256
    const int m0 = mtile * 16;
    const int g   = lane >> 2;
    const int tig = lane & 3;

    // A fragments: [split][kstep][4]
    unsigned A[2][4][4];
    #pragma unroll
    for (int ks = 0; ks < 4; ++ks) {
        int kc = ks * 16 + 2 * tig;
        const char* bh = (const char*)sZh;
        const char* bl = (const char*)sZl;
        A[0][ks][0] = *(const unsigned*)(bh + (m0 + g) * 144 + kc * 2);
        A[0][ks][1] = *(const unsigned*)(bh + (m0 + g + 8) * 144 + kc * 2);
        A[0][ks][2] = *(const unsigned*)(bh + (m0 + g) * 144 + (kc + 8) * 2);
        A[0][ks][3] = *(const unsigned*)(bh + (m0 + g + 8) * 144 + (kc + 8) * 2);
        A[1][ks][0] = *(const unsigned*)(bl + (m0 + g) * 144 + kc * 2);
        A[1][ks][1] = *(const unsigned*)(bl + (m0 + g + 8) * 144 + kc * 2);
        A[1][ks][2] = *(const unsigned*)(bl + (m0 + g) * 144 + (kc + 8) * 2);
        A[1][ks][3] = *(const unsigned*)(bl + (m0 + g + 8) * 144 + (kc + 8) * 2);
    }
    const float zq0 = sZsq[m0 + g];
    const float zq1 = sZsq[m0 + g + 8];

    float best0 = 3.4e38f, sec0 = 3.4e38f, best1 = 3.4e38f, sec1 = 3.4e38f;
    int k0 = 0, k1 = 0;

    const int nbase0 = nhalf * 256;
    for (int nt = 0; nt < 32; ++nt) {
        const int nb = nbase0 + nt * 8;
        float c0 = 0.f, c1 = 0.f, c2 = 0.f, c3 = 0.f;
        #pragma unroll
        for (int ks = 0; ks < 4; ++ks) {
            const int boff = (nb + g) * 144 + (ks * 16 + 2 * tig) * 2;
            unsigned bh0 = *(const unsigned*)((const char*)sEh + boff);
            unsigned bh1 = *(const unsigned*)((const char*)sEh + boff + 16);
            unsigned bl0 = *(const unsigned*)((const char*)sEl + boff);
            unsigned bl1 = *(const unsigned*)((const char*)sEl + boff + 16);
            mma16816(c0, c1, c2, c3, A[0][ks][0], A[0][ks][1], A[0][ks][2], A[0][ks][3], bh0, bh1); // zhi*ehi
            mma16816(c0, c1, c2, c3, A[1][ks][0], A[1][ks][1], A[1][ks][2], A[1][ks][3], bh0, bh1); // zlo*ehi
            mma16816(c0, c1, c2, c3, A[0][ks][0], A[0][ks][1], A[0][ks][2], A[0][ks][3], bl0, bl1); // zhi*elo
        }
        const int kA = nb + 2 * tig;
        const float2 en = *(const float2*)&sEN[kA];
        float s00 = (zq0 + en.x) + c0;
        float s01 = (zq0 + en.y) + c1;
        float s10 = (zq1 + en.x) + c2;
        float s11 = (zq1 + en.y) + c3;
        // row0 updates (ascending k within lane -> strict < keeps lowest)
        if (s00 < best0) { sec0 = best0; best0 = s00; k0 = kA; } else if (s00 < sec0) sec0 = s00;
        if (s01 < best0) { sec0 = best0; best0 = s01; k0 = kA + 1; } else if (s01 < sec0) sec0 = s01;
        if (s10 < best1) { sec1 = best1; best1 = s10; k1 = kA; } else if (s10 < sec1) sec1 = s10;
        if (s11 < best1) { sec1 = best1; best1 = s11; k1 = kA + 1; } else if (s11 < sec1) sec1 = s11;
    }

    // cross-lane merge within 4-lane groups (xor 1, 2)
    #pragma unroll
    for (int d = 1; d <= 2; d <<= 1) {
        float ob = __shfl_xor_sync(0xffffffffu, best0, d);
        int   ok = __shfl_xor_sync(0xffffffffu, k0, d);
        float os = __shfl_xor_sync(0xffffffffu, sec0, d);
        float worse = fmaxf(best0, ob);
        float news  = fminf(worse, fminf(sec0, os));
        bool take = (ob < best0) || (ob == best0 && ok < k0);
        best0 = take ? ob : best0; k0 = take ? ok : k0; sec0 = news;

        ob = __shfl_xor_sync(0xffffffffu, best1, d);
        ok = __shfl_xor_sync(0xffffffffu, k1, d);
        os = __shfl_xor_sync(0xffffffffu, sec1, d);
        worse = fmaxf(best1, ob);
        news  = fminf(worse, fminf(sec1, os));
        take = (ob < best1) || (ob == best1 && ok < k1);
        best1 = take ? ob : best1; k1 = take ? ok : k1; sec1 = news;
    }
    if (tig == 0) {
        int r0 = m0 + g, r1 = m0 + g + 8;
        sBest[r0 * 2 + nhalf] = best0; sK[r0 * 2 + nhalf] = k0; sSec[r0 * 2 + nhalf] = sec0;
        sBest[r1 * 2 + nhalf] = best1; sK[r1 * 2 + nhalf] = k1; sSec[r1 * 2 + nhalf] = sec1;
    }
    __syncthreads();

    // ---- per-row finalize ----
    double dacc = 0.0;
    if (tid < 128) {
        const int row = tid;
        float b0 = sBest[row * 2],     s0 = sSec[row * 2];     int kk0 = sK[row * 2];
        float b1 = sBest[row * 2 + 1], s1 = sSec[row * 2 + 1]; int kk1 = sK[row * 2 + 1];
        bool take1 = (b1 < b0);                     // tie -> half0 (lower k)
        float bb = take1 ? b1 : b0;
        int   kk = take1 ? kk1 : kk0;
        float ss = fminf(fmaxf(b0, b1), fminf(s0, s1));
        if (ss - bb > TAU) {
            atomicAdd(&sHist[kk], 1);
            dacc = (double)bb;                      // dist == score
            const float4* er = (const float4*)(e + kk * DDIM);
            float* o = out + 1 + zbase + row;
            #pragma unroll
            for (int q = 0; q < 16; ++q) {
                float4 v = __ldg(er + q);
                o[(4 * q)     * 4096] = v.x;
                o[(4 * q + 1) * 4096] = v.y;
                o[(4 * q + 2) * 4096] = v.z;
                o[(4 * q + 3) * 4096] = v.w;
            }
        } else {
            int idx = atomicAdd(&g_fb_count, 1);
            g_fb_list[idx] = p0 + row;
        }
    }
    // fp64 reduce of dacc over tid<128 (4 warps)
    #pragma unroll
    for (int off = 16; off > 0; off >>= 1)
        dacc += __shfl_down_sync(0xffffffffu, dacc, off);
    if (tid < 128 && lane == 0) sW[w] = dacc;
    __syncthreads();
    if (tid == 0) g_sse[blockIdx.x] = ((sW[0] + sW[1]) + sW[2]) + sW[3];
    {
        int c = sHist[tid];
        if (c) atomicAdd(&g_counts[tid], c);
    }
}

// ===========================================================================
// Fallback: exact fp32 rescore of uncertain positions (verbatim R3 math)
// ===========================================================================
#define FB_SMEM (131072 + 2048)
__global__ __launch_bounds__(512, 1)
void fb_kernel(const float* __restrict__ z, const float* __restrict__ e,
               float* __restrict__ out) {
    extern __shared__ char sm[];
    ulonglong2* sE  = (ulonglong2*)sm;
    float*      sEN = (float*)(sm + 131072);
    const int tid = threadIdx.x;
    const int gt  = blockIdx.x * 512 + tid;

    const int cnt = g_fb_count;
    if (cnt == 0) { g_fb_sse[gt] = 0.0; return; }

    for (int i = tid; i < KCODES * 16; i += 512) {
        int k = i >> 4, q = i & 15;
        float4 v = *(const float4*)(e + k * DDIM + q * 4);
        ulonglong2 ww;
        ww.x = pack2(-2.f * v.x, -2.f * v.y);
        ww.y = pack2(-2.f * v.z, -2.f * v.w);
        sE[i] = ww;
    }
    {
        const float4* row = (const float4*)(e + tid * DDIM);
        float s = 0.f;
        #pragma unroll
        for (int q = 0; q < 16; ++q) {
            float4 v = row[q];
            s = fmaf(v.x, v.x, s); s = fmaf(v.y, v.y, s);
            s = fmaf(v.z, v.z, s); s = fmaf(v.w, v.w, s);
        }
        sEN[tid] = s;
    }
    __syncthreads();

    double acc = 0.0;
    for (int i = gt; i < cnt; i += FB_THREADS_TOTAL) {
        const int p = g_fb_list[i];
        const int zoff = (p >> 12) * 262144 + (p & 4095);
        unsigned long long zz[32];
        float zsq = 0.f;
        #pragma unroll
        for (int q = 0; q < 32; ++q) {
            float f0 = __ldg(z + zoff + (2 * q) * 4096);
            float f1 = __ldg(z + zoff + (2 * q + 1) * 4096);
            zz[q] = pack2(f0, f1);
            zsq = fmaf(f0, f0, zsq);
            zsq = fmaf(f1, f1, zsq);
        }
        float best = 3.4e38f; int bestk = 0;
        #pragma unroll 2
        for (int k = 0; k < KCODES; ++k) {
            const ulonglong2* ep = sE + k * 16;
            unsigned long long c0 = 0ull, c1 = 0ull;
            #pragma unroll
            for (int q = 0; q < 16; ++q) {
                ulonglong2 ev = ep[q];
                c0 = ffma2(zz[2 * q],     ev.x, c0);
                c1 = ffma2(zz[2 * q + 1], ev.y, c1);
            }
            unsigned long long s2 = fadd2(c0, c1);
            float s  = lo2(s2) + hi2(s2);
            float sc = (zsq + sEN[k]) + s;
            if (sc < best) { best = sc; bestk = k; }
        }
        atomicAdd(&g_counts[bestk], 1);
        acc += (double)best;
        const ulonglong2* ep = sE + bestk * 16;
        float* o = out + 1 + zoff;
        #pragma unroll
        for (int q = 0; q < 16; ++q) {
            ulonglong2 ev = ep[q];
            o[(4 * q)     * 4096] = -0.5f * lo2(ev.x);
            o[(4 * q + 1) * 4096] = -0.5f * hi2(ev.x);
            o[(4 * q + 2) * 4096] = -0.5f * lo2(ev.y);
            o[(4 * q + 3) * 4096] = -0.5f * hi2(ev.y);
        }
    }
    g_fb_sse[gt] = acc;
}

// ===========================================================================
// Finalize: perplexity + loss; reset counters for graph replay
// ===========================================================================
__global__ void finalize_kernel(float* __restrict__ out, int out_size) {
    __shared__ double sh[KCODES];
    const int t = threadIdx.x;   // 512
    double em = (double)g_counts[t] * (1.0 / 131072.0);
    g_counts[t] = 0;
    double x = em + 1e-10;
    sh[t] = x * log(x);
    __syncthreads();
    for (int s = KCODES / 2; s > 0; s >>= 1) {
        if (t < s) sh[t] += sh[t + s];
        __syncthreads();
    }
    double ent = sh[0];
    __syncthreads();
    sh[t] = (g_sse[t] + g_sse[t + 512]) + (g_fb_sse[t] + g_fb_sse[t + 512])
          + (g_fb_sse[t + 1024] + g_fb_sse[t + 1536]);
    __syncthreads();
    for (int s = KCODES / 2; s > 0; s >>= 1) {
        if (t < s) sh[t] += sh[t + s];
        __syncthreads();
    }
    if (t == 0) {
        g_fb_count = 0;
        double mse = sh[0] / 8388608.0;
        out[0]            = (float)(1.25 * mse);
        out[out_size - 1] = (float)exp(-ent);
    }
}

// ---------------------------------------------------------------------------
extern "C" void kernel_launch(void* const* d_in, const int* in_sizes, int n_in,
                              void* d_out, int out_size) {
    const float* z = (const float*)d_in[0];
    const float* e = (const float*)d_in[1];
    if (n_in >= 2 && in_sizes[0] == KCODES * DDIM && in_sizes[1] == N_POS * 16) {
        const float* tmp = z; z = e; e = tmp;
    }
    cudaFuncSetAttribute(vq_mma_kernel, cudaFuncAttributeMaxDynamicSharedMemorySize, MAIN_SMEM);
    cudaFuncSetAttribute(fb_kernel,     cudaFuncAttributeMaxDynamicSharedMemorySize, FB_SMEM);

    vq_mma_kernel<<<MMA_BLOCKS, 512, MAIN_SMEM>>>(z, e, (float*)d_out);
    fb_kernel<<<4, 512, FB_SMEM>>>(z, e, (float*)d_out);
    finalize_kernel<<<1, KCODES>>>((float*)d_out, out_size);
}

// round 8
// speedup vs baseline: 3.8192x; 3.8192x over previous
#include <cuda_runtime.h>
#include <cuda_bf16.h>
#include <math.h>

#define N_POS   131072
#define KCODES  512
#define DDIM    64
#define GRID    1024             // 128 positions per CTA
#define NTHR    512
#define TAU     2e-4f

// ---- device scratch (no allocation allowed) ----
__device__ int    g_counts[KCODES];
__device__ double g_sse[GRID];

// ---------- helpers ----------
static __device__ __forceinline__ void mma16816(float& c0, float& c1, float& c2, float& c3,
                                                unsigned a0, unsigned a1, unsigned a2, unsigned a3,
                                                unsigned b0, unsigned b1) {
    asm volatile("mma.sync.aligned.m16n8k16.row.col.f32.bf16.bf16.f32 "
                 "{%0,%1,%2,%3}, {%4,%5,%6,%7}, {%8,%9}, {%0,%1,%2,%3};"
                 : "+f"(c0), "+f"(c1), "+f"(c2), "+f"(c3)
                 : "r"(a0), "r"(a1), "r"(a2), "r"(a3), "r"(b0), "r"(b1));
}

// ---------- smem layout (bytes) ----------
#define SE_H   0                        // e_hi bf16 [512][72]  (pitch 144B)
#define SE_L   73728                    // e_lo
#define SZ_H   147456                   // z_hi bf16 [128][72]  (fb: fsc [8][512]f)
#define SZ_L   165888                   // z_lo                 (fb: fzs [8][64]f + fzq[8])
#define SEN    184320                   // float[512]
#define SZSQP  186368                   // float[512]
#define SZSQ   188416                   // float[128]
#define SBEST  188928                   // float[256]  (row*2 + nhalf)
#define SKIDX  189952                   // int[256]
#define SSEC   190976                   // float[256]
#define SHIST  192000                   // int[512]
#define SWSUM  194048                   // double[4]
#define S_FBC  194080                   // int
#define S_FBR  194084                   // int[128]
#define S_FBK2 194596                   // int[16]
#define S_FBS2 194660                   // float[16]
#define S_FBK  194724                   // int[8]
#define S_FBSC 194756                   // float[8]
#define MAIN_SMEM 194816

// ===========================================================================
// Main kernel: bf16 split-MMA filter (4-way tile ILP) + margin + in-CTA
// exact fp32 fallback.  1024 CTAs x 512 threads; CTA = 128 positions x 512 codes.
// ===========================================================================
__global__ __launch_bounds__(NTHR, 1)
void vq_mma_kernel(const float* __restrict__ z, const float* __restrict__ e,
                   float* __restrict__ out) {
    extern __shared__ char sm[];
    __nv_bfloat16* sEh = (__nv_bfloat16*)(sm + SE_H);
    __nv_bfloat16* sEl = (__nv_bfloat16*)(sm + SE_L);
    __nv_bfloat16* sZh = (__nv_bfloat16*)(sm + SZ_H);
    __nv_bfloat16* sZl = (__nv_bfloat16*)(sm + SZ_L);
    float*  sEN   = (float*)(sm + SEN);
    float*  sZsqP = (float*)(sm + SZSQP);
    float*  sZsq  = (float*)(sm + SZSQ);
    float*  sBest = (float*)(sm + SBEST);
    int*    sK    = (int*)(sm + SKIDX);
    float*  sSec  = (float*)(sm + SSEC);
    int*    sHist = (int*)(sm + SHIST);
    double* sW    = (double*)(sm + SWSUM);
    int*    sFbC  = (int*)(sm + S_FBC);
    int*    sFbR  = (int*)(sm + S_FBR);
    int*    sFbK2 = (int*)(sm + S_FBK2);
    float*  sFbS2 = (float*)(sm + S_FBS2);
    int*    sFbK  = (int*)(sm + S_FBK);
    float*  sFbSC = (float*)(sm + S_FBSC);

    const int tid  = threadIdx.x;
    const int lane = tid & 31;
    const int w    = tid >> 5;
    const int p0   = blockIdx.x * 128;
    const int zbase = (p0 >> 12) * 262144 + (p0 & 4095);

    if (tid == 0) *sFbC = 0;

    // ---- stage codebook: -2e as bf16 hi/lo, eN fp32 (validated R5 staging) ----
    {
        const int n = tid;                       // 512 threads = 512 codes
        const float* row = e + n * DDIM;
        float s = 0.f;
        #pragma unroll 8
        for (int d = 0; d < DDIM; ++d) {
            float v = row[d];
            s = fmaf(v, v, s);
            float m = -2.f * v;
            __nv_bfloat16 h = __float2bfloat16_rn(m);
            __nv_bfloat16 l = __float2bfloat16_rn(m - __bfloat162float(h));
            sEh[n * 72 + d] = h;
            sEl[n * 72 + d] = l;
        }
        sEN[n]  = s;
        sHist[n] = 0;
    }
    // ---- stage z: bf16 hi/lo + zsq partials ----
    {
        const int row  = tid & 127;
        const int part = tid >> 7;               // 4 parts of 16 dims
        float s = 0.f;
        #pragma unroll
        for (int j = 0; j < 16; ++j) {
            int d = part * 16 + j;
            float v = __ldg(z + zbase + row + d * 4096);
            s = fmaf(v, v, s);
            __nv_bfloat16 h = __float2bfloat16_rn(v);
            __nv_bfloat16 l = __float2bfloat16_rn(v - __bfloat162float(h));
            sZh[row * 72 + d] = h;
            sZl[row * 72 + d] = l;
        }
        sZsqP[part * 128 + row] = s;
    }
    __syncthreads();
    if (tid < 128)
        sZsq[tid] = ((sZsqP[tid] + sZsqP[128 + tid]) + sZsqP[256 + tid]) + sZsqP[384 + tid];
    __syncthreads();

    // ---- MMA streaming: warp = (m-tile, code-half); 4 n-tiles in flight ----
    const int mtile = w & 7;
    const int nhalf = w >> 3;
    const int m0  = mtile * 16;
    const int g   = lane >> 2;
    const int tig = lane & 3;

    unsigned A[2][4][4];                         // [split][kstep][frag]
    #pragma unroll
    for (int ks = 0; ks < 4; ++ks) {
        int kc = ks * 16 + 2 * tig;
        const char* bh = (const char*)sZh;
        const char* bl = (const char*)sZl;
        A[0][ks][0] = *(const unsigned*)(bh + (m0 + g) * 144 + kc * 2);
        A[0][ks][1] = *(const unsigned*)(bh + (m0 + g + 8) * 144 + kc * 2);
        A[0][ks][2] = *(const unsigned*)(bh + (m0 + g) * 144 + (kc + 8) * 2);
        A[0][ks][3] = *(const unsigned*)(bh + (m0 + g + 8) * 144 + (kc + 8) * 2);
        A[1][ks][0] = *(const unsigned*)(bl + (m0 + g) * 144 + kc * 2);
        A[1][ks][1] = *(const unsigned*)(bl + (m0 + g + 8) * 144 + kc * 2);
        A[1][ks][2] = *(const unsigned*)(bl + (m0 + g) * 144 + (kc + 8) * 2);
        A[1][ks][3] = *(const unsigned*)(bl + (m0 + g + 8) * 144 + (kc + 8) * 2);
    }
    const float zq0 = sZsq[m0 + g];
    const float zq1 = sZsq[m0 + g + 8];

    float best0 = 3.4e38f, sec0 = 3.4e38f, best1 = 3.4e38f, sec1 = 3.4e38f;
    int k0 = 0, k1 = 0;

    const int nbase0 = nhalf * 256;
    for (int nt4 = 0; nt4 < 8; ++nt4) {
        const int nb = nbase0 + nt4 * 32;
        float c[4][4];
        #pragma unroll
        for (int t = 0; t < 4; ++t) { c[t][0] = c[t][1] = c[t][2] = c[t][3] = 0.f; }
        #pragma unroll
        for (int ks = 0; ks < 4; ++ks) {
            unsigned bh[4][2], bl[4][2];
            #pragma unroll
            for (int t = 0; t < 4; ++t) {
                const int boff = (nb + t * 8 + g) * 144 + (ks * 16 + 2 * tig) * 2;
                bh[t][0] = *(const unsigned*)((const char*)sEh + boff);
                bh[t][1] = *(const unsigned*)((const char*)sEh + boff + 16);
                bl[t][0] = *(const unsigned*)((const char*)sEl + boff);
                bl[t][1] = *(const unsigned*)((const char*)sEl + boff + 16);
            }
            #pragma unroll
            for (int t = 0; t < 4; ++t)
                mma16816(c[t][0], c[t][1], c[t][2], c[t][3],
                         A[0][ks][0], A[0][ks][1], A[0][ks][2], A[0][ks][3],
                         bh[t][0], bh[t][1]);                 // zhi * ehi
            #pragma unroll
            for (int t = 0; t < 4; ++t)
                mma16816(c[t][0], c[t][1], c[t][2], c[t][3],
                         A[1][ks][0], A[1][ks][1], A[1][ks][2], A[1][ks][3],
                         bh[t][0], bh[t][1]);                 // zlo * ehi
            #pragma unroll
            for (int t = 0; t < 4; ++t)
                mma16816(c[t][0], c[t][1], c[t][2], c[t][3],
                         A[0][ks][0], A[0][ks][1], A[0][ks][2], A[0][ks][3],
                         bl[t][0], bl[t][1]);                 // zhi * elo
        }
        #pragma unroll
        for (int t = 0; t < 4; ++t) {
            const int kA = nb + t * 8 + 2 * tig;
            const float2 en = *(const float2*)&sEN[kA];
            float s00 = (zq0 + en.x) + c[t][0];
            float s01 = (zq0 + en.y) + c[t][1];
            float s10 = (zq1 + en.x) + c[t][2];
            float s11 = (zq1 + en.y) + c[t][3];
            if (s00 < best0) { sec0 = best0; best0 = s00; k0 = kA; } else if (s00 < sec0) sec0 = s00;
            if (s01 < best0) { sec0 = best0; best0 = s01; k0 = kA + 1; } else if (s01 < sec0) sec0 = s01;
            if (s10 < best1) { sec1 = best1; best1 = s10; k1 = kA; } else if (s10 < sec1) sec1 = s10;
            if (s11 < best1) { sec1 = best1; best1 = s11; k1 = kA + 1; } else if (s11 < sec1) sec1 = s11;
        }
    }

    // cross-lane merge within 4-lane groups (validated R5 code)
    #pragma unroll
    for (int d = 1; d <= 2; d <<= 1) {
        float ob = __shfl_xor_sync(0xffffffffu, best0, d);
        int   ok = __shfl_xor_sync(0xffffffffu, k0, d);
        float os = __shfl_xor_sync(0xffffffffu, sec0, d);
        float worse = fmaxf(best0, ob);
        float news  = fminf(worse, fminf(sec0, os));
        bool take = (ob < best0) || (ob == best0 && ok < k0);
        best0 = take ? ob : best0; k0 = take ? ok : k0; sec0 = news;

        ob = __shfl_xor_sync(0xffffffffu, best1, d);
        ok = __shfl_xor_sync(0xffffffffu, k1, d);
        os = __shfl_xor_sync(0xffffffffu, sec1, d);
        worse = fmaxf(best1, ob);
        news  = fminf(worse, fminf(sec1, os));
        take = (ob < best1) || (ob == best1 && ok < k1);
        best1 = take ? ob : best1; k1 = take ? ok : k1; sec1 = news;
    }
    if (tig == 0) {
        int r0 = m0 + g, r1 = m0 + g + 8;
        sBest[r0 * 2 + nhalf] = best0; sK[r0 * 2 + nhalf] = k0; sSec[r0 * 2 + nhalf] = sec0;
        sBest[r1 * 2 + nhalf] = best1; sK[r1 * 2 + nhalf] = k1; sSec[r1 * 2 + nhalf] = sec1;
    }
    __syncthreads();

    // ---- per-row merge + margin test (validated R5 code; fb goes to smem list) ----
    double dacc = 0.0;
    if (tid < 128) {
        const int row = tid;
        float b0 = sBest[row * 2],     s0 = sSec[row * 2];     int kk0 = sK[row * 2];
        float b1 = sBest[row * 2 + 1], s1 = sSec[row * 2 + 1]; int kk1 = sK[row * 2 + 1];
        bool take1 = (b1 < b0);                     // tie -> half0 (lower k)
        float bb = take1 ? b1 : b0;
        int   kk = take1 ? kk1 : kk0;
        float ss = fminf(fmaxf(b0, b1), fminf(s0, s1));
        if (ss - bb > TAU) {
            atomicAdd(&sHist[kk], 1);
            dacc = (double)bb;
            const float4* er = (const float4*)(e + kk * DDIM);
            float* o = out + 1 + zbase + row;
            #pragma unroll
            for (int q = 0; q < 16; ++q) {
                float4 v = __ldg(er + q);
                o[(4 * q)     * 4096] = v.x;
                o[(4 * q + 1) * 4096] = v.y;
                o[(4 * q + 2) * 4096] = v.z;
                o[(4 * q + 3) * 4096] = v.w;
            }
        } else {
            int idx = atomicAdd(sFbC, 1);
            sFbR[idx] = row;
        }
    }
    __syncthreads();

    // ---- in-CTA exact fp32 fallback (association identical to validated R5 fb) ----
    const int nfb = *sFbC;
    double fbacc = 0.0;
    float* fsc = (float*)(sm + SZ_H);          // [8][512] scores (bf16 A region dead)
    float* fzs = (float*)(sm + SZ_L);          // [8][64] z rows fp32
    float* fzq = (float*)(sm + SZ_L + 2048);   // [8]
    for (int base = 0; base < nfb; base += 8) {
        const int nb = min(8, nfb - base);
        {
            int r = tid >> 6, d = tid & 63;
            if (r < nb)
                fzs[r * 64 + d] = __ldg(z + zbase + sFbR[base + r] + d * 4096);
        }
        __syncthreads();
        if (tid < nb) {
            float s = 0.f;
            #pragma unroll 8
            for (int d = 0; d < 64; ++d) { float f = fzs[tid * 64 + d]; s = fmaf(f, f, s); }
            fzq[tid] = s;
        }
        __syncthreads();
        {
            // thread = code; 4 chains per row exactly as validated R5 fb
            float alo[8], ahi[8], blo[8], bhi[8];
            #pragma unroll
            for (int r = 0; r < 8; ++r) { alo[r] = ahi[r] = blo[r] = bhi[r] = 0.f; }
            float s_en = 0.f;
            const float4* er = (const float4*)(e + tid * DDIM);
            #pragma unroll
            for (int q = 0; q < 16; ++q) {
                float4 v = __ldg(er + q);
                s_en = fmaf(v.x, v.x, s_en); s_en = fmaf(v.y, v.y, s_en);
                s_en = fmaf(v.z, v.z, s_en); s_en = fmaf(v.w, v.w, s_en);
                float mx = -2.f * v.x, my = -2.f * v.y, mz = -2.f * v.z, mw = -2.f * v.w;
                #pragma unroll
                for (int r = 0; r < 8; ++r) {
                    float4 zv = *(const float4*)&fzs[r * 64 + 4 * q];
                    alo[r] = fmaf(zv.x, mx, alo[r]);
                    ahi[r] = fmaf(zv.y, my, ahi[r]);
                    blo[r] = fmaf(zv.z, mz, blo[r]);
                    bhi[r] = fmaf(zv.w, mw, bhi[r]);
                }
            }
            #pragma unroll
            for (int r = 0; r < 8; ++r) {
                float s = (alo[r] + blo[r]) + (ahi[r] + bhi[r]);
                fsc[r * 512 + tid] = (fzq[r] + s_en) + s;
            }
        }
        __syncthreads();
        {
            int r = tid >> 6, j = tid & 63;
            float bs = 3.4e38f; int bk = 1 << 30;
            if (r < nb) {
                #pragma unroll
                for (int i = 0; i < 8; ++i) {
                    int k = j + 64 * i;
                    float s = fsc[r * 512 + k];
                    if (s < bs || (s == bs && k < bk)) { bs = s; bk = k; }
                }
            }
            #pragma unroll
            for (int off = 16; off > 0; off >>= 1) {
                float os = __shfl_down_sync(0xffffffffu, bs, off);
                int   ok = __shfl_down_sync(0xffffffffu, bk, off);
                if (os < bs || (os == bs && ok < bk)) { bs = os; bk = ok; }
            }
            if (lane == 0 && r < nb) {
                int half = (tid >> 5) & 1;
                sFbK2[r * 2 + half] = bk;
                sFbS2[r * 2 + half] = bs;
            }
        }
        __syncthreads();
        if (tid < nb) {
            int kk0 = sFbK2[tid * 2], kk1 = sFbK2[tid * 2 + 1];
            float s0 = sFbS2[tid * 2], s1 = sFbS2[tid * 2 + 1];
            bool t1 = (s1 < s0) || (s1 == s0 && kk1 < kk0);
            int kk = t1 ? kk1 : kk0;
            sFbK[tid]  = kk;
            sFbSC[tid] = t1 ? s1 : s0;
            atomicAdd(&sHist[kk], 1);
        }
        __syncthreads();
        if (tid == 0) {
            for (int r = 0; r < nb; ++r) fbacc += (double)sFbSC[r];
        }
        if (tid < 128) {
            int r = tid >> 4, q = tid & 15;
            if (r < nb) {
                int kk = sFbK[r];
                float4 v = __ldg((const float4*)(e + kk * DDIM) + q);
                float* o = out + 1 + zbase + sFbR[base + r];
                o[(4 * q)     * 4096] = v.x;
                o[(4 * q + 1) * 4096] = v.y;
                o[(4 * q + 2) * 4096] = v.z;
                o[(4 * q + 3) * 4096] = v.w;
            }
        }
        __syncthreads();
    }

    // ---- reductions out ----
    #pragma unroll
    for (int off = 16; off > 0; off >>= 1)
        dacc += __shfl_down_sync(0xffffffffu, dacc, off);
    if (tid < 128 && lane == 0) sW[w] = dacc;
    __syncthreads();
    if (tid == 0)
        g_sse[blockIdx.x] = ((((sW[0] + sW[1]) + sW[2]) + sW[3])) + fbacc;
    {
        int c = sHist[tid];
        if (c) atomicAdd(&g_counts[tid], c);
    }
}

// ===========================================================================
// Finalize: perplexity + loss (fp64, validated R3 math); resets counters
// ===========================================================================
__global__ void finalize_kernel(float* __restrict__ out, int out_size) {
    __shared__ double ep[16];
    __shared__ double sp[16];
    const int t = threadIdx.x;            // 512
    const int lane = t & 31, w = t >> 5;
    double em = (double)g_counts[t] * (1.0 / 131072.0);
    g_counts[t] = 0;
    double x = em + 1e-10;
    double term = x * log(x);
    double ds = g_sse[t] + g_sse[t + 512];
    #pragma unroll
    for (int off = 16; off > 0; off >>= 1) {
        term += __shfl_down_sync(0xffffffffu, term, off);
        ds   += __shfl_down_sync(0xffffffffu, ds, off);
    }
    if (lane == 0) { ep[w] = term; sp[w] = ds; }
    __syncthreads();
    if (t == 0) {
        double ent = 0.0; double sse = 0.0;
        #pragma unroll
        for (int i = 0; i < 16; ++i) { ent += ep[i]; sse += sp[i]; }
        double mse = sse / 8388608.0;
        out[0]            = (float)(1.25 * mse);
        out[out_size - 1] = (float)exp(-ent);
    }
}

// ---------------------------------------------------------------------------
extern "C" void kernel_launch(void* const* d_in, const int* in_sizes, int n_in,
                              void* d_out, int out_size) {
    const float* z = (const float*)d_in[0];
    const float* e = (const float*)d_in[1];
    if (n_in >= 2 && in_sizes[0] == KCODES * DDIM && in_sizes[1] == N_POS * 16) {
        const float* tmp = z; z = e; e = tmp;
    }
    cudaFuncSetAttribute(vq_mma_kernel, cudaFuncAttributeMaxDynamicSharedMemorySize, MAIN_SMEM);

    vq_mma_kernel<<<GRID, NTHR, MAIN_SMEM>>>(z, e, (float*)d_out);
    finalize_kernel<<<1, KCODES>>>((float*)d_out, out_size);
}

// round 9
// speedup vs baseline: 5.6606x; 1.4821x over previous
#include <cuda_runtime.h>
#include <cuda_bf16.h>
#include <math.h>

#define N_POS   131072
#define KCODES  512
#define DDIM    64
#define GRID    1024             // 128 positions per CTA
#define NTHR    512
#define TAU     2e-4f

// ---- device scratch (no allocation allowed) ----
__device__ uint4  g_ebh4[4608];    // bf16 hi of -2e, [k][pitch72]  (73728 B)
__device__ uint4  g_ebl4[4608];    // bf16 lo
__device__ float  g_en[KCODES];
__device__ int    g_counts[KCODES];
__device__ double g_sse[GRID];
__device__ unsigned g_done;        // zero-init; self-resetting

// ---------- helpers ----------
static __device__ __forceinline__ void mma16816(float& c0, float& c1, float& c2, float& c3,
                                                unsigned a0, unsigned a1, unsigned a2, unsigned a3,
                                                unsigned b0, unsigned b1) {
    asm volatile("mma.sync.aligned.m16n8k16.row.col.f32.bf16.bf16.f32 "
                 "{%0,%1,%2,%3}, {%4,%5,%6,%7}, {%8,%9}, {%0,%1,%2,%3};"
                 : "+f"(c0), "+f"(c1), "+f"(c2), "+f"(c3)
                 : "r"(a0), "r"(a1), "r"(a2), "r"(a3), "r"(b0), "r"(b1));
}

// ---------- smem layout (bytes) ----------
#define SE_H   0                        // e_hi bf16 [512][72]  (pitch 144B)
#define SE_L   73728                    // e_lo
#define SZ_H   147456                   // z_hi bf16 [128][72]  (fb: fsc [8][512]f)
#define SZ_L   165888                   // z_lo                 (fb: fzs [8][64]f + fzq[8])
#define SEN    184320                   // float[512]
#define SZSQP  186368                   // float[512]
#define SZSQ   188416                   // float[128]
#define SBEST  188928                   // float[256]
#define SKIDX  189952                   // int[256]
#define SSEC   190976                   // float[256]
#define SHIST  192000                   // int[512]
#define S_WS   194048                   // double[16]
#define S_FBC  194176                   // int
#define S_FBR  194180                   // int[128]
#define S_FBK2 194692                   // int[16]
#define S_FBS2 194756                   // float[16]
#define S_FBK  194820                   // int[8]
#define S_FBSC 194852                   // float[8]
#define S_ROWK 194884                   // int[128]
#define S_WS2  195400                   // double[16]  (8-aligned)
#define MAIN_SMEM 195528

// ===========================================================================
// Prep: codebook -> bf16 hi/lo of -2e at pitch 72 (global) + eN
// ===========================================================================
__global__ void prep_kernel(const float* __restrict__ e) {
    int t = blockIdx.x * blockDim.x + threadIdx.x;   // 64 x 512 = 32768
    int k = t >> 6, d = t & 63;
    float v = e[t];
    float m = -2.f * v;
    __nv_bfloat16 h = __float2bfloat16_rn(m);
    __nv_bfloat16 l = __float2bfloat16_rn(m - __bfloat162float(h));
    ((__nv_bfloat16*)g_ebh4)[k * 72 + d] = h;
    ((__nv_bfloat16*)g_ebl4)[k * 72 + d] = l;
    if (blockIdx.x == 0) {
        const float4* row = (const float4*)(e + threadIdx.x * DDIM);
        float s = 0.f;
        #pragma unroll
        for (int q = 0; q < 16; ++q) {
            float4 w = __ldg(row + q);
            s = fmaf(w.x, w.x, s); s = fmaf(w.y, w.y, s);
            s = fmaf(w.z, w.z, s); s = fmaf(w.w, w.w, s);
        }
        g_en[threadIdx.x] = s;
    }
}

// ===========================================================================
// Main: bf16 split-MMA filter (4-way tile ILP) + margin + in-CTA exact
// fallback + fused last-CTA finalize.
// ===========================================================================
__global__ __launch_bounds__(NTHR, 1)
void vq_mma_kernel(const float* __restrict__ z, const float* __restrict__ e,
                   float* __restrict__ out, int out_size) {
    extern __shared__ char sm[];
    __nv_bfloat16* sZh = (__nv_bfloat16*)(sm + SZ_H);
    __nv_bfloat16* sZl = (__nv_bfloat16*)(sm + SZ_L);
    float*  sEN   = (float*)(sm + SEN);
    float*  sZsqP = (float*)(sm + SZSQP);
    float*  sZsq  = (float*)(sm + SZSQ);
    float*  sBest = (float*)(sm + SBEST);
    int*    sK    = (int*)(sm + SKIDX);
    float*  sSec  = (float*)(sm + SSEC);
    int*    sHist = (int*)(sm + SHIST);
    double* sW    = (double*)(sm + S_WS);
    double* sW2   = (double*)(sm + S_WS2);
    int*    sFbC  = (int*)(sm + S_FBC);
    int*    sFbR  = (int*)(sm + S_FBR);
    int*    sFbK2 = (int*)(sm + S_FBK2);
    float*  sFbS2 = (float*)(sm + S_FBS2);
    int*    sFbK  = (int*)(sm + S_FBK);
    float*  sFbSC = (float*)(sm + S_FBSC);
    int*    sRowK = (int*)(sm + S_ROWK);

    const int tid  = threadIdx.x;
    const int lane = tid & 31;
    const int w    = tid >> 5;
    const int p0   = blockIdx.x * 128;
    const int zbase = (p0 >> 12) * 262144 + (p0 & 4095);

    if (tid == 0) *sFbC = 0;

    // ---- stage codebook: wide copy of precomputed bf16 hi/lo + eN ----
    {
        uint4* dEh = (uint4*)(sm + SE_H);
        uint4* dEl = (uint4*)(sm + SE_L);
        #pragma unroll
        for (int i = 0; i < 9; ++i) {              // 4608 = 512*9
            int idx = tid + NTHR * i;
            dEh[idx] = g_ebh4[idx];
            dEl[idx] = g_ebl4[idx];
        }
        sEN[tid]  = g_en[tid];
        sHist[tid] = 0;
    }
    // ---- stage z: bf16 hi/lo + zsq partials (validated) ----
    {
        const int row  = tid & 127;
        const int part = tid >> 7;
        float s = 0.f;
        #pragma unroll
        for (int j = 0; j < 16; ++j) {
            int d = part * 16 + j;
            float v = __ldg(z + zbase + row + d * 4096);
            s = fmaf(v, v, s);
            __nv_bfloat16 h = __float2bfloat16_rn(v);
            __nv_bfloat16 l = __float2bfloat16_rn(v - __bfloat162float(h));
            sZh[row * 72 + d] = h;
            sZl[row * 72 + d] = l;
        }
        sZsqP[part * 128 + row] = s;
    }
    __syncthreads();
    if (tid < 128)
        sZsq[tid] = ((sZsqP[tid] + sZsqP[128 + tid]) + sZsqP[256 + tid]) + sZsqP[384 + tid];
    __syncthreads();

    // ---- MMA streaming (validated R8 code) ----
    const int mtile = w & 7;
    const int nhalf = w >> 3;
    const int m0  = mtile * 16;
    const int g   = lane >> 2;
    const int tig = lane & 3;
    const __nv_bfloat16* sEh = (const __nv_bfloat16*)(sm + SE_H);
    const __nv_bfloat16* sEl = (const __nv_bfloat16*)(sm + SE_L);

    unsigned A[2][4][4];
    #pragma unroll
    for (int ks = 0; ks < 4; ++ks) {
        int kc = ks * 16 + 2 * tig;
        const char* bh = (const char*)sZh;
        const char* bl = (const char*)sZl;
        A[0][ks][0] = *(const unsigned*)(bh + (m0 + g) * 144 + kc * 2);
        A[0][ks][1] = *(const unsigned*)(bh + (m0 + g + 8) * 144 + kc * 2);
        A[0][ks][2] = *(const unsigned*)(bh + (m0 + g) * 144 + (kc + 8) * 2);
        A[0][ks][3] = *(const unsigned*)(bh + (m0 + g + 8) * 144 + (kc + 8) * 2);
        A[1][ks][0] = *(const unsigned*)(bl + (m0 + g) * 144 + kc * 2);
        A[1][ks][1] = *(const unsigned*)(bl + (m0 + g + 8) * 144 + kc * 2);
        A[1][ks][2] = *(const unsigned*)(bl + (m0 + g) * 144 + (kc + 8) * 2);
        A[1][ks][3] = *(const unsigned*)(bl + (m0 + g + 8) * 144 + (kc + 8) * 2);
    }
    const float zq0 = sZsq[m0 + g];
    const float zq1 = sZsq[m0 + g + 8];

    float best0 = 3.4e38f, sec0 = 3.4e38f, best1 = 3.4e38f, sec1 = 3.4e38f;
    int k0 = 0, k1 = 0;

    const int nbase0 = nhalf * 256;
    for (int nt4 = 0; nt4 < 8; ++nt4) {
        const int nb = nbase0 + nt4 * 32;
        float c[4][4];
        #pragma unroll
        for (int t = 0; t < 4; ++t) { c[t][0] = c[t][1] = c[t][2] = c[t][3] = 0.f; }
        #pragma unroll
        for (int ks = 0; ks < 4; ++ks) {
            unsigned bh[4][2], bl[4][2];
            #pragma unroll
            for (int t = 0; t < 4; ++t) {
                const int boff = (nb + t * 8 + g) * 144 + (ks * 16 + 2 * tig) * 2;
                bh[t][0] = *(const unsigned*)((const char*)sEh + boff);
                bh[t][1] = *(const unsigned*)((const char*)sEh + boff + 16);
                bl[t][0] = *(const unsigned*)((const char*)sEl + boff);
                bl[t][1] = *(const unsigned*)((const char*)sEl + boff + 16);
            }
            #pragma unroll
            for (int t = 0; t < 4; ++t)
                mma16816(c[t][0], c[t][1], c[t][2], c[t][3],
                         A[0][ks][0], A[0][ks][1], A[0][ks][2], A[0][ks][3],
                         bh[t][0], bh[t][1]);
            #pragma unroll
            for (int t = 0; t < 4; ++t)
                mma16816(c[t][0], c[t][1], c[t][2], c[t][3],
                         A[1][ks][0], A[1][ks][1], A[1][ks][2], A[1][ks][3],
                         bh[t][0], bh[t][1]);
            #pragma unroll
            for (int t = 0; t < 4; ++t)
                mma16816(c[t][0], c[t][1], c[t][2], c[t][3],
                         A[0][ks][0], A[0][ks][1], A[0][ks][2], A[0][ks][3],
                         bl[t][0], bl[t][1]);
        }
        #pragma unroll
        for (int t = 0; t < 4; ++t) {
            const int kA = nb + t * 8 + 2 * tig;
            const float2 en = *(const float2*)&sEN[kA];
            float s00 = (zq0 + en.x) + c[t][0];
            float s01 = (zq0 + en.y) + c[t][1];
            float s10 = (zq1 + en.x) + c[t][2];
            float s11 = (zq1 + en.y) + c[t][3];
            if (s00 < best0) { sec0 = best0; best0 = s00; k0 = kA; } else if (s00 < sec0) sec0 = s00;
            if (s01 < best0) { sec0 = best0; best0 = s01; k0 = kA + 1; } else if (s01 < sec0) sec0 = s01;
            if (s10 < best1) { sec1 = best1; best1 = s10; k1 = kA; } else if (s10 < sec1) sec1 = s10;
            if (s11 < best1) { sec1 = best1; best1 = s11; k1 = kA + 1; } else if (s11 < sec1) sec1 = s11;
        }
    }

    #pragma unroll
    for (int d = 1; d <= 2; d <<= 1) {
        float ob = __shfl_xor_sync(0xffffffffu, best0, d);
        int   ok = __shfl_xor_sync(0xffffffffu, k0, d);
        float os = __shfl_xor_sync(0xffffffffu, sec0, d);
        float worse = fmaxf(best0, ob);
        float news  = fminf(worse, fminf(sec0, os));
        bool take = (ob < best0) || (ob == best0 && ok < k0);
        best0 = take ? ob : best0; k0 = take ? ok : k0; sec0 = news;

        ob = __shfl_xor_sync(0xffffffffu, best1, d);
        ok = __shfl_xor_sync(0xffffffffu, k1, d);
        os = __shfl_xor_sync(0xffffffffu, sec1, d);
        worse = fmaxf(best1, ob);
        news  = fminf(worse, fminf(sec1, os));
        take = (ob < best1) || (ob == best1 && ok < k1);
        best1 = take ? ob : best1; k1 = take ? ok : k1; sec1 = news;
    }
    if (tig == 0) {
        int r0 = m0 + g, r1 = m0 + g + 8;
        sBest[r0 * 2 + nhalf] = best0; sK[r0 * 2 + nhalf] = k0; sSec[r0 * 2 + nhalf] = sec0;
        sBest[r1 * 2 + nhalf] = best1; sK[r1 * 2 + nhalf] = k1; sSec[r1 * 2 + nhalf] = sec1;
    }
    __syncthreads();

    // ---- per-row merge + margin test -> sRowK (scatter deferred to all threads) ----
    double dacc = 0.0;
    if (tid < 128) {
        const int row = tid;
        float b0 = sBest[row * 2],     s0 = sSec[row * 2];     int kk0 = sK[row * 2];
        float b1 = sBest[row * 2 + 1], s1 = sSec[row * 2 + 1]; int kk1 = sK[row * 2 + 1];
        bool take1 = (b1 < b0);
        float bb = take1 ? b1 : b0;
        int   kk = take1 ? kk1 : kk0;
        float ss = fminf(fmaxf(b0, b1), fminf(s0, s1));
        if (ss - bb > TAU) {
            atomicAdd(&sHist[kk], 1);
            dacc = (double)bb;
            sRowK[row] = kk;
        } else {
            int idx = atomicAdd(sFbC, 1);
            sFbR[idx] = row;
            sRowK[row] = -1;
        }
    }
    __syncthreads();

    // ---- z_q scatter: all 512 threads, coalesced (lanes = consecutive rows) ----
    {
        const int r = tid & 127, part = tid >> 7;
        const int kk = sRowK[r];
        if (kk >= 0) {
            const float4* er = (const float4*)(e + kk * DDIM) + part * 4;
            float* o = out + 1 + zbase + r;
            #pragma unroll
            for (int q = 0; q < 4; ++q) {
                float4 v = __ldg(er + q);
                int d0 = part * 16 + 4 * q;
                o[(d0)     * 4096] = v.x;
                o[(d0 + 1) * 4096] = v.y;
                o[(d0 + 2) * 4096] = v.z;
                o[(d0 + 3) * 4096] = v.w;
            }
        }
    }
    __syncthreads();

    // ---- in-CTA exact fp32 fallback (validated R8 code) ----
    const int nfb = *sFbC;
    double fbacc = 0.0;
    float* fsc = (float*)(sm + SZ_H);
    float* fzs = (float*)(sm + SZ_L);
    float* fzq = (float*)(sm + SZ_L + 2048);
    for (int base = 0; base < nfb; base += 8) {
        const int nb = min(8, nfb - base);
        {
            int r = tid >> 6, d = tid & 63;
            if (r < nb)
                fzs[r * 64 + d] = __ldg(z + zbase + sFbR[base + r] + d * 4096);
        }
        __syncthreads();
        if (tid < nb) {
            float s = 0.f;
            #pragma unroll 8
            for (int d = 0; d < 64; ++d) { float f = fzs[tid * 64 + d]; s = fmaf(f, f, s); }
            fzq[tid] = s;
        }
        __syncthreads();
        {
            float alo[8], ahi[8], blo[8], bhi[8];
            #pragma unroll
            for (int r = 0; r < 8; ++r) { alo[r] = ahi[r] = blo[r] = bhi[r] = 0.f; }
            float s_en = 0.f;
            const float4* er = (const float4*)(e + tid * DDIM);
            #pragma unroll
            for (int q = 0; q < 16; ++q) {
                float4 v = __ldg(er + q);
                s_en = fmaf(v.x, v.x, s_en); s_en = fmaf(v.y, v.y, s_en);
                s_en = fmaf(v.z, v.z, s_en); s_en = fmaf(v.w, v.w, s_en);
                float mx = -2.f * v.x, my = -2.f * v.y, mz = -2.f * v.z, mw = -2.f * v.w;
                #pragma unroll
                for (int r = 0; r < 8; ++r) {
                    float4 zv = *(const float4*)&fzs[r * 64 + 4 * q];
                    alo[r] = fmaf(zv.x, mx, alo[r]);
                    ahi[r] = fmaf(zv.y, my, ahi[r]);
                    blo[r] = fmaf(zv.z, mz, blo[r]);
                    bhi[r] = fmaf(zv.w, mw, bhi[r]);
                }
            }
            #pragma unroll
            for (int r = 0; r < 8; ++r) {
                float s = (alo[r] + blo[r]) + (ahi[r] + bhi[r]);
                fsc[r * 512 + tid] = (fzq[r] + s_en) + s;
            }
        }
        __syncthreads();
        {
            int r = tid >> 6, j = tid & 63;
            float bs = 3.4e38f; int bk = 1 << 30;
            if (r < nb) {
                #pragma unroll
                for (int i = 0; i < 8; ++i) {
                    int k = j + 64 * i;
                    float s = fsc[r * 512 + k];
                    if (s < bs || (s == bs && k < bk)) { bs = s; bk = k; }
                }
            }
            #pragma unroll
            for (int off = 16; off > 0; off >>= 1) {
                float os = __shfl_down_sync(0xffffffffu, bs, off);
                int   ok = __shfl_down_sync(0xffffffffu, bk, off);
                if (os < bs || (os == bs && ok < bk)) { bs = os; bk = ok; }
            }
            if (lane == 0 && r < nb) {
                int half = (tid >> 5) & 1;
                sFbK2[r * 2 + half] = bk;
                sFbS2[r * 2 + half] = bs;
            }
        }
        __syncthreads();
        if (tid < nb) {
            int kk0 = sFbK2[tid * 2], kk1 = sFbK2[tid * 2 + 1];
            float s0 = sFbS2[tid * 2], s1 = sFbS2[tid * 2 + 1];
            bool t1 = (s1 < s0) || (s1 == s0 && kk1 < kk0);
            int kk = t1 ? kk1 : kk0;
            sFbK[tid]  = kk;
            sFbSC[tid] = t1 ? s1 : s0;
            atomicAdd(&sHist[kk], 1);
        }
        __syncthreads();
        if (tid == 0) {
            for (int r = 0; r < nb; ++r) fbacc += (double)sFbSC[r];
        }
        if (tid < 128) {
            int r = tid >> 4, q = tid & 15;
            if (r < nb) {
                int kk = sFbK[r];
                float4 v = __ldg((const float4*)(e + kk * DDIM) + q);
                float* o = out + 1 + zbase + sFbR[base + r];
                o[(4 * q)     * 4096] = v.x;
                o[(4 * q + 1) * 4096] = v.y;
                o[(4 * q + 2) * 4096] = v.z;
                o[(4 * q + 3) * 4096] = v.w;
            }
        }
        __syncthreads();
    }

    // ---- per-CTA reductions out ----
    #pragma unroll
    for (int off = 16; off > 0; off >>= 1)
        dacc += __shfl_down_sync(0xffffffffu, dacc, off);
    if (tid < 128 && lane == 0) sW[w] = dacc;
    __syncthreads();
    if (tid == 0)
        g_sse[blockIdx.x] = ((((sW[0] + sW[1]) + sW[2]) + sW[3])) + fbacc;
    {
        int c = sHist[tid];
        if (c) atomicAdd(&g_counts[tid], c);
    }

    // ---- fused finalize: last CTA to finish does loss + perplexity ----
    __shared__ int sLast;
    __threadfence();
    __syncthreads();
    if (tid == 0) sLast = (atomicAdd(&g_done, 1u) == GRID - 1u) ? 1 : 0;
    __syncthreads();
    if (sLast) {
        __threadfence();
        double em = (double)g_counts[tid] * (1.0 / 131072.0);
        g_counts[tid] = 0;
        double x = em + 1e-10;
        double term = x * log(x);
        double ds = g_sse[tid] + g_sse[tid + 512];
        #pragma unroll
        for (int off = 16; off > 0; off >>= 1) {
            term += __shfl_down_sync(0xffffffffu, term, off);
            ds   += __shfl_down_sync(0xffffffffu, ds, off);
        }
        if (lane == 0) { sW[w] = ds; sW2[w] = term; }
        __syncthreads();
        if (tid == 0) {
            double ent = 0.0, sse = 0.0;
            #pragma unroll
            for (int i = 0; i < 16; ++i) { ent += sW2[i]; sse += sW[i]; }
            double mse = sse / 8388608.0;
            out[0]            = (float)(1.25 * mse);
            out[out_size - 1] = (float)exp(-ent);
            g_done = 0;                       // replay-safe reset
        }
    }
}

// ---------------------------------------------------------------------------
extern "C" void kernel_launch(void* const* d_in, const int* in_sizes, int n_in,
                              void* d_out, int out_size) {
    const float* z = (const float*)d_in[0];
    const float* e = (const float*)d_in[1];
    if (n_in >= 2 && in_sizes[0] == KCODES * DDIM && in_sizes[1] == N_POS * DDIM) {
        const float* tmp = z; z = e; e = tmp;      // defensive order swap
    }
    cudaFuncSetAttribute(vq_mma_kernel, cudaFuncAttributeMaxDynamicSharedMemorySize, MAIN_SMEM);

    prep_kernel<<<64, 512>>>(e);
    vq_mma_kernel<<<GRID, NTHR, MAIN_SMEM>>>(z, e, (float*)d_out, out_size);
}

// round 10
// speedup vs baseline: 5.7757x; 1.0203x over previous
#include <cuda_runtime.h>
#include <cuda_bf16.h>
#include <math.h>

#define N_POS   131072
#define KCODES  512
#define DDIM    64
#define GRID    1024             // 128 positions per CTA
#define NTHR    512
#define TAU     2e-4f

// ---- device scratch (no allocation allowed) ----
__device__ uint4  g_ebh4[4608];    // bf16 hi of -2e, [k][pitch72]  (73728 B)
__device__ uint4  g_ebl4[4608];    // bf16 lo
__device__ float  g_en[KCODES];
__device__ int    g_counts[KCODES];
__device__ double g_sse[GRID];
__device__ unsigned g_done;        // zero-init; self-resetting

// ---------- helpers ----------
static __device__ __forceinline__ void mma16816(float& c0, float& c1, float& c2, float& c3,
                                                unsigned a0, unsigned a1, unsigned a2, unsigned a3,
                                                unsigned b0, unsigned b1) {
    asm volatile("mma.sync.aligned.m16n8k16.row.col.f32.bf16.bf16.f32 "
                 "{%0,%1,%2,%3}, {%4,%5,%6,%7}, {%8,%9}, {%0,%1,%2,%3};"
                 : "+f"(c0), "+f"(c1), "+f"(c2), "+f"(c3)
                 : "r"(a0), "r"(a1), "r"(a2), "r"(a3), "r"(b0), "r"(b1));
}
#define LDSM4(d0, d1, d2, d3, addr)                                          \
    asm volatile("ldmatrix.sync.aligned.m8n8.x4.shared.b16 {%0,%1,%2,%3}, [%4];" \
                 : "=r"(d0), "=r"(d1), "=r"(d2), "=r"(d3) : "r"(addr))

static __device__ __forceinline__ unsigned smem_u32(const void* p) {
    unsigned a;
    asm("{ .reg .u64 t; cvta.to.shared.u64 t, %1; cvt.u32.u64 %0, t; }" : "=r"(a) : "l"(p));
    return a;
}

// ---------- smem layout (bytes) ----------
#define SE_H   0                        // e_hi bf16 [512][72]  (pitch 144B)
#define SE_L   73728                    // e_lo
#define SZ_H   147456                   // z_hi bf16 [128][72]  (fb: fsc [8][512]f)
#define SZ_L   165888                   // z_lo                 (fb: fzs [8][64]f + fzq[8])
#define SEN    184320                   // float[512]
#define SZSQP  186368                   // float[512]
#define SZSQ   188416                   // float[128]
#define SBEST  188928                   // float[256]
#define SKIDX  189952                   // int[256]
#define SSEC   190976                   // float[256]
#define SHIST  192000                   // int[512]
#define S_WS   194048                   // double[16]
#define S_FBC  194176                   // int
#define S_FBR  194180                   // int[128]
#define S_FBK2 194692                   // int[16]
#define S_FBS2 194756                   // float[16]
#define S_FBK  194820                   // int[8]
#define S_FBSC 194852                   // float[8]
#define S_ROWK 194884                   // int[128]
#define S_WS2  195400                   // double[16]  (8-aligned)
#define MAIN_SMEM 195528

// ===========================================================================
// Prep: codebook -> bf16 hi/lo of -2e at pitch 72 (global) + eN
// ===========================================================================
__global__ void prep_kernel(const float* __restrict__ e) {
    int t = blockIdx.x * blockDim.x + threadIdx.x;   // 64 x 512 = 32768
    int k = t >> 6, d = t & 63;
    float v = e[t];
    float m = -2.f * v;
    __nv_bfloat16 h = __float2bfloat16_rn(m);
    __nv_bfloat16 l = __float2bfloat16_rn(m - __bfloat162float(h));
    ((__nv_bfloat16*)g_ebh4)[k * 72 + d] = h;
    ((__nv_bfloat16*)g_ebl4)[k * 72 + d] = l;
    if (blockIdx.x == 0) {
        const float4* row = (const float4*)(e + threadIdx.x * DDIM);
        float s = 0.f;
        #pragma unroll
        for (int q = 0; q < 16; ++q) {
            float4 w = __ldg(row + q);
            s = fmaf(w.x, w.x, s); s = fmaf(w.y, w.y, s);
            s = fmaf(w.z, w.z, s); s = fmaf(w.w, w.w, s);
        }
        g_en[threadIdx.x] = s;
    }
}

// ===========================================================================
// Main: bf16 split-MMA filter (4-way tile ILP, LDSM B loads) + margin +
// in-CTA exact fallback + fused last-CTA finalize.
// ===========================================================================
__global__ __launch_bounds__(NTHR, 1)
void vq_mma_kernel(const float* __restrict__ z, const float* __restrict__ e,
                   float* __restrict__ out, int out_size) {
    extern __shared__ char sm[];
    __nv_bfloat16* sZh = (__nv_bfloat16*)(sm + SZ_H);
    __nv_bfloat16* sZl = (__nv_bfloat16*)(sm + SZ_L);
    float*  sEN   = (float*)(sm + SEN);
    float*  sZsqP = (float*)(sm + SZSQP);
    float*  sZsq  = (float*)(sm + SZSQ);
    float*  sBest = (float*)(sm + SBEST);
    int*    sK    = (int*)(sm + SKIDX);
    float*  sSec  = (float*)(sm + SSEC);
    int*    sHist = (int*)(sm + SHIST);
    double* sW    = (double*)(sm + S_WS);
    double* sW2   = (double*)(sm + S_WS2);
    int*    sFbC  = (int*)(sm + S_FBC);
    int*    sFbR  = (int*)(sm + S_FBR);
    int*    sFbK2 = (int*)(sm + S_FBK2);
    float*  sFbS2 = (float*)(sm + S_FBS2);
    int*    sFbK  = (int*)(sm + S_FBK);
    float*  sFbSC = (float*)(sm + S_FBSC);
    int*    sRowK = (int*)(sm + S_ROWK);

    const int tid  = threadIdx.x;
    const int lane = tid & 31;
    const int w    = tid >> 5;
    const int p0   = blockIdx.x * 128;
    const int zbase = (p0 >> 12) * 262144 + (p0 & 4095);

    if (tid == 0) *sFbC = 0;

    // ---- stage codebook: wide copy of precomputed bf16 hi/lo + eN ----
    {
        uint4* dEh = (uint4*)(sm + SE_H);
        uint4* dEl = (uint4*)(sm + SE_L);
        #pragma unroll
        for (int i = 0; i < 9; ++i) {              // 4608 = 512*9
            int idx = tid + NTHR * i;
            dEh[idx] = g_ebh4[idx];
            dEl[idx] = g_ebl4[idx];
        }
        sEN[tid]  = g_en[tid];
        sHist[tid] = 0;
    }
    // ---- stage z: bf16 hi/lo + zsq partials (validated) ----
    {
        const int row  = tid & 127;
        const int part = tid >> 7;
        float s = 0.f;
        #pragma unroll
        for (int j = 0; j < 16; ++j) {
            int d = part * 16 + j;
            float v = __ldg(z + zbase + row + d * 4096);
            s = fmaf(v, v, s);
            __nv_bfloat16 h = __float2bfloat16_rn(v);
            __nv_bfloat16 l = __float2bfloat16_rn(v - __bfloat162float(h));
            sZh[row * 72 + d] = h;
            sZl[row * 72 + d] = l;
        }
        sZsqP[part * 128 + row] = s;
    }
    __syncthreads();
    if (tid < 128)
        sZsq[tid] = ((sZsqP[tid] + sZsqP[128 + tid]) + sZsqP[256 + tid]) + sZsqP[384 + tid];
    __syncthreads();

    // ---- MMA streaming: warp = (m-tile, code-half); 4 n-tiles in flight ----
    const int mtile = w & 7;
    const int nhalf = w >> 3;
    const int m0  = mtile * 16;
    const int g   = lane >> 2;
    const int tig = lane & 3;

    unsigned A[2][4][4];
    #pragma unroll
    for (int ks = 0; ks < 4; ++ks) {
        int kc = ks * 16 + 2 * tig;
        const char* bh = (const char*)sZh;
        const char* bl = (const char*)sZl;
        A[0][ks][0] = *(const unsigned*)(bh + (m0 + g) * 144 + kc * 2);
        A[0][ks][1] = *(const unsigned*)(bh + (m0 + g + 8) * 144 + kc * 2);
        A[0][ks][2] = *(const unsigned*)(bh + (m0 + g) * 144 + (kc + 8) * 2);
        A[0][ks][3] = *(const unsigned*)(bh + (m0 + g + 8) * 144 + (kc + 8) * 2);
        A[1][ks][0] = *(const unsigned*)(bl + (m0 + g) * 144 + kc * 2);
        A[1][ks][1] = *(const unsigned*)(bl + (m0 + g + 8) * 144 + kc * 2);
        A[1][ks][2] = *(const unsigned*)(bl + (m0 + g) * 144 + (kc + 8) * 2);
        A[1][ks][3] = *(const unsigned*)(bl + (m0 + g + 8) * 144 + (kc + 8) * 2);
    }
    const float zq0 = sZsq[m0 + g];
    const float zq1 = sZsq[m0 + g + 8];

    float best0 = 3.4e38f, sec0 = 3.4e38f, best1 = 3.4e38f, sec1 = 3.4e38f;
    int k0 = 0, k1 = 0;

    // LDSM lane address: matrix mi = lane>>3 -> (tile-in-pair = mi>>1, khalf = mi&1), row = lane&7
    const unsigned smemBase = smem_u32(sm);
    const unsigned ldsmRow = (unsigned)(((lane >> 4) * 8 + (lane & 7)) * 144
                                        + ((lane >> 3) & 1) * 16);
    const int nbase0 = nhalf * 256;
    const unsigned aEh0 = smemBase + SE_H + ldsmRow + (unsigned)nbase0 * 144u;

    for (int nt4 = 0; nt4 < 8; ++nt4) {
        const int nb = nbase0 + nt4 * 32;
        float c[4][4];
        #pragma unroll
        for (int t = 0; t < 4; ++t) { c[t][0] = c[t][1] = c[t][2] = c[t][3] = 0.f; }
        #pragma unroll
        for (int ks = 0; ks < 4; ++ks) {
            const unsigned bA = aEh0 + (unsigned)(nt4 * 4608 + ks * 32);
            unsigned bh[8], bl[8];
            LDSM4(bh[0], bh[1], bh[2], bh[3], bA);                         // tiles 0,1 (b0,b1)
            LDSM4(bh[4], bh[5], bh[6], bh[7], bA + 2304u);                 // tiles 2,3
            LDSM4(bl[0], bl[1], bl[2], bl[3], bA + (SE_L - SE_H));
            LDSM4(bl[4], bl[5], bl[6], bl[7], bA + (SE_L - SE_H) + 2304u);
            #pragma unroll
            for (int t = 0; t < 4; ++t)
                mma16816(c[t][0], c[t][1], c[t][2], c[t][3],
                         A[0][ks][0], A[0][ks][1], A[0][ks][2], A[0][ks][3],
                         bh[2 * t], bh[2 * t + 1]);                        // zhi * ehi
            #pragma unroll
            for (int t = 0; t < 4; ++t)
                mma16816(c[t][0], c[t][1], c[t][2], c[t][3],
                         A[1][ks][0], A[1][ks][1], A[1][ks][2], A[1][ks][3],
                         bh[2 * t], bh[2 * t + 1]);                        // zlo * ehi
            #pragma unroll
            for (int t = 0; t < 4; ++t)
                mma16816(c[t][0], c[t][1], c[t][2], c[t][3],
                         A[0][ks][0], A[0][ks][1], A[0][ks][2], A[0][ks][3],
                         bl[2 * t], bl[2 * t + 1]);                        // zhi * elo
        }
        #pragma unroll
        for (int t = 0; t < 4; ++t) {
            const int kA = nb + t * 8 + 2 * tig;
            const float2 en = *(const float2*)&sEN[kA];
            float s00 = (zq0 + en.x) + c[t][0];
            float s01 = (zq0 + en.y) + c[t][1];
            float s10 = (zq1 + en.x) + c[t][2];
            float s11 = (zq1 + en.y) + c[t][3];
            if (s00 < best0) { sec0 = best0; best0 = s00; k0 = kA; } else if (s00 < sec0) sec0 = s00;
            if (s01 < best0) { sec0 = best0; best0 = s01; k0 = kA + 1; } else if (s01 < sec0) sec0 = s01;
            if (s10 < best1) { sec1 = best1; best1 = s10; k1 = kA; } else if (s10 < sec1) sec1 = s10;
            if (s11 < best1) { sec1 = best1; best1 = s11; k1 = kA + 1; } else if (s11 < sec1) sec1 = s11;
        }
    }

    #pragma unroll
    for (int d = 1; d <= 2; d <<= 1) {
        float ob = __shfl_xor_sync(0xffffffffu, best0, d);
        int   ok = __shfl_xor_sync(0xffffffffu, k0, d);
        float os = __shfl_xor_sync(0xffffffffu, sec0, d);
        float worse = fmaxf(best0, ob);
        float news  = fminf(worse, fminf(sec0, os));
        bool take = (ob < best0) || (ob == best0 && ok < k0);
        best0 = take ? ob : best0; k0 = take ? ok : k0; sec0 = news;

        ob = __shfl_xor_sync(0xffffffffu, best1, d);
        ok = __shfl_xor_sync(0xffffffffu, k1, d);
        os = __shfl_xor_sync(0xffffffffu, sec1, d);
        worse = fmaxf(best1, ob);
        news  = fminf(worse, fminf(sec1, os));
        take = (ob < best1) || (ob == best1 && ok < k1);
        best1 = take ? ob : best1; k1 = take ? ok : k1; sec1 = news;
    }
    if (tig == 0) {
        int r0 = m0 + g, r1 = m0 + g + 8;
        sBest[r0 * 2 + nhalf] = best0; sK[r0 * 2 + nhalf] = k0; sSec[r0 * 2 + nhalf] = sec0;
        sBest[r1 * 2 + nhalf] = best1; sK[r1 * 2 + nhalf] = k1; sSec[r1 * 2 + nhalf] = sec1;
    }
    __syncthreads();

    // ---- per-row merge + margin test -> sRowK ----
    double dacc = 0.0;
    if (tid < 128) {
        const int row = tid;
        float b0 = sBest[row * 2],     s0 = sSec[row * 2];     int kk0 = sK[row * 2];
        float b1 = sBest[row * 2 + 1], s1 = sSec[row * 2 + 1]; int kk1 = sK[row * 2 + 1];
        bool take1 = (b1 < b0);
        float bb = take1 ? b1 : b0;
        int   kk = take1 ? kk1 : kk0;
        float ss = fminf(fmaxf(b0, b1), fminf(s0, s1));
        if (ss - bb > TAU) {
            atomicAdd(&sHist[kk], 1);
            dacc = (double)bb;
            sRowK[row] = kk;
        } else {
            int idx = atomicAdd(sFbC, 1);
            sFbR[idx] = row;
            sRowK[row] = -1;
        }
    }
    __syncthreads();

    // ---- z_q scatter: all 512 threads, coalesced ----
    {
        const int r = tid & 127, part = tid >> 7;
        const int kk = sRowK[r];
        if (kk >= 0) {
            const float4* er = (const float4*)(e + kk * DDIM) + part * 4;
            float* o = out + 1 + zbase + r;
            #pragma unroll
            for (int q = 0; q < 4; ++q) {
                float4 v = __ldg(er + q);
                int d0 = part * 16 + 4 * q;
                o[(d0)     * 4096] = v.x;
                o[(d0 + 1) * 4096] = v.y;
                o[(d0 + 2) * 4096] = v.z;
                o[(d0 + 3) * 4096] = v.w;
            }
        }
    }
    __syncthreads();

    // ---- in-CTA exact fp32 fallback (validated) ----
    const int nfb = *sFbC;
    double fbacc = 0.0;
    float* fsc = (float*)(sm + SZ_H);
    float* fzs = (float*)(sm + SZ_L);
    float* fzq = (float*)(sm + SZ_L + 2048);
    for (int base = 0; base < nfb; base += 8) {
        const int nb = min(8, nfb - base);
        {
            int r = tid >> 6, d = tid & 63;
            if (r < nb)
                fzs[r * 64 + d] = __ldg(z + zbase + sFbR[base + r] + d * 4096);
        }
        __syncthreads();
        if (tid < nb) {
            float s = 0.f;
            #pragma unroll 8
            for (int d = 0; d < 64; ++d) { float f = fzs[tid * 64 + d]; s = fmaf(f, f, s); }
            fzq[tid] = s;
        }
        __syncthreads();
        {
            float alo[8], ahi[8], blo[8], bhi[8];
            #pragma unroll
            for (int r = 0; r < 8; ++r) { alo[r] = ahi[r] = blo[r] = bhi[r] = 0.f; }
            float s_en = 0.f;
            const float4* er = (const float4*)(e + tid * DDIM);
            #pragma unroll
            for (int q = 0; q < 16; ++q) {
                float4 v = __ldg(er + q);
                s_en = fmaf(v.x, v.x, s_en); s_en = fmaf(v.y, v.y, s_en);
                s_en = fmaf(v.z, v.z, s_en); s_en = fmaf(v.w, v.w, s_en);
                float mx = -2.f * v.x, my = -2.f * v.y, mz = -2.f * v.z, mw = -2.f * v.w;
                #pragma unroll
                for (int r = 0; r < 8; ++r) {
                    float4 zv = *(const float4*)&fzs[r * 64 + 4 * q];
                    alo[r] = fmaf(zv.x, mx, alo[r]);
                    ahi[r] = fmaf(zv.y, my, ahi[r]);
                    blo[r] = fmaf(zv.z, mz, blo[r]);
                    bhi[r] = fmaf(zv.w, mw, bhi[r]);
                }
            }
            #pragma unroll
            for (int r = 0; r < 8; ++r) {
                float s = (alo[r] + blo[r]) + (ahi[r] + bhi[r]);
                fsc[r * 512 + tid] = (fzq[r] + s_en) + s;
            }
        }
        __syncthreads();
        {
            int r = tid >> 6, j = tid & 63;
            float bs = 3.4e38f; int bk = 1 << 30;
            if (r < nb) {
                #pragma unroll
                for (int i = 0; i < 8; ++i) {
                    int k = j + 64 * i;
                    float s = fsc[r * 512 + k];
                    if (s < bs || (s == bs && k < bk)) { bs = s; bk = k; }
                }
            }
            #pragma unroll
            for (int off = 16; off > 0; off >>= 1) {
                float os = __shfl_down_sync(0xffffffffu, bs, off);
                int   ok = __shfl_down_sync(0xffffffffu, bk, off);
                if (os < bs || (os == bs && ok < bk)) { bs = os; bk = ok; }
            }
            if (lane == 0 && r < nb) {
                int half = (tid >> 5) & 1;
                sFbK2[r * 2 + half] = bk;
                sFbS2[r * 2 + half] = bs;
            }
        }
        __syncthreads();
        if (tid < nb) {
            int kk0 = sFbK2[tid * 2], kk1 = sFbK2[tid * 2 + 1];
            float s0 = sFbS2[tid * 2], s1 = sFbS2[tid * 2 + 1];
            bool t1 = (s1 < s0) || (s1 == s0 && kk1 < kk0);
            int kk = t1 ? kk1 : kk0;
            sFbK[tid]  = kk;
            sFbSC[tid] = t1 ? s1 : s0;
            atomicAdd(&sHist[kk], 1);
        }
        __syncthreads();
        if (tid == 0) {
            for (int r = 0; r < nb; ++r) fbacc += (double)sFbSC[r];
        }
        if (tid < 128) {
            int r = tid >> 4, q = tid & 15;
            if (r < nb) {
                int kk = sFbK[r];
                float4 v = __ldg((const float4*)(e + kk * DDIM) + q);
                float* o = out + 1 + zbase + sFbR[base + r];
                o[(4 * q)     * 4096] = v.x;
                o[(4 * q + 1) * 4096] = v.y;
                o[(4 * q + 2) * 4096] = v.z;
                o[(4 * q + 3) * 4096] = v.w;
            }
        }
        __syncthreads();
    }

    // ---- per-CTA reductions out ----
    #pragma unroll
    for (int off = 16; off > 0; off >>= 1)
        dacc += __shfl_down_sync(0xffffffffu, dacc, off);
    if (tid < 128 && lane == 0) sW[w] = dacc;
    __syncthreads();
    if (tid == 0)
        g_sse[blockIdx.x] = ((((sW[0] + sW[1]) + sW[2]) + sW[3])) + fbacc;
    {
        int c = sHist[tid];
        if (c) atomicAdd(&g_counts[tid], c);
    }

    // ---- fused finalize: last CTA does loss + perplexity ----
    __shared__ int sLast;
    __threadfence();
    __syncthreads();
    if (tid == 0) sLast = (atomicAdd(&g_done, 1u) == GRID - 1u) ? 1 : 0;
    __syncthreads();
    if (sLast) {
        __threadfence();
        double em = (double)g_counts[tid] * (1.0 / 131072.0);
        g_counts[tid] = 0;
        double x = em + 1e-10;
        double term = x * log(x);
        double ds = g_sse[tid] + g_sse[tid + 512];
        #pragma unroll
        for (int off = 16; off > 0; off >>= 1) {
            term += __shfl_down_sync(0xffffffffu, term, off);
            ds   += __shfl_down_sync(0xffffffffu, ds, off);
        }
        if (lane == 0) { sW[w] = ds; sW2[w] = term; }
        __syncthreads();
        if (tid == 0) {
            double ent = 0.0, sse = 0.0;
            #pragma unroll
            for (int i = 0; i < 16; ++i) { ent += sW2[i]; sse += sW[i]; }
            double mse = sse / 8388608.0;
            out[0]            = (float)(1.25 * mse);
            out[out_size - 1] = (float)exp(-ent);
            g_done = 0;                       // replay-safe reset
        }
    }
}

// ---------------------------------------------------------------------------
extern "C" void kernel_launch(void* const* d_in, const int* in_sizes, int n_in,
                              void* d_out, int out_size) {
    const float* z = (const float*)d_in[0];
    const float* e = (const float*)d_in[1];
    if (n_in >= 2 && in_sizes[0] == KCODES * DDIM && in_sizes[1] == N_POS * DDIM) {
        const float* tmp = z; z = e; e = tmp;      // defensive order swap
    }
    cudaFuncSetAttribute(vq_mma_kernel, cudaFuncAttributeMaxDynamicSharedMemorySize, MAIN_SMEM);

    prep_kernel<<<64, 512>>>(e);
    vq_mma_kernel<<<GRID, NTHR, MAIN_SMEM>>>(z, e, (float*)d_out, out_size);
}

// round 11
// speedup vs baseline: 7.2633x; 1.2576x over previous
#include <cuda_runtime.h>
#include <cuda_bf16.h>
#include <math.h>

#define N_POS   131072
#define KCODES  512
#define DDIM    64
#define GRID    1024             // 128 positions per CTA
#define NTHR    512
#define TAU     2e-4f

// ---- device scratch (no allocation allowed) ----
__device__ uint4  g_ebh4[4608];    // bf16 hi of -2e, [k][pitch72]  (73728 B)
__device__ float  g_en[KCODES];
__device__ int    g_counts[KCODES];
__device__ double g_sse[GRID];
__device__ unsigned g_done;        // zero-init; self-resetting

// ---------- helpers ----------
static __device__ __forceinline__ void mma16816(float& c0, float& c1, float& c2, float& c3,
                                                unsigned a0, unsigned a1, unsigned a2, unsigned a3,
                                                unsigned b0, unsigned b1) {
    asm volatile("mma.sync.aligned.m16n8k16.row.col.f32.bf16.bf16.f32 "
                 "{%0,%1,%2,%3}, {%4,%5,%6,%7}, {%8,%9}, {%0,%1,%2,%3};"
                 : "+f"(c0), "+f"(c1), "+f"(c2), "+f"(c3)
                 : "r"(a0), "r"(a1), "r"(a2), "r"(a3), "r"(b0), "r"(b1));
}
#define LDSM4(d0, d1, d2, d3, addr)                                          \
    asm volatile("ldmatrix.sync.aligned.m8n8.x4.shared.b16 {%0,%1,%2,%3}, [%4];" \
                 : "=r"(d0), "=r"(d1), "=r"(d2), "=r"(d3) : "r"(addr))

static __device__ __forceinline__ unsigned smem_u32(const void* p) {
    unsigned a;
    asm("{ .reg .u64 t; cvta.to.shared.u64 t, %1; cvt.u32.u64 %0, t; }" : "=r"(a) : "l"(p));
    return a;
}

// ---------- smem layout (bytes), fixed regions: 115456 total ----------
#define SE_H   0                 // e_hi bf16 [512][72] pitch 144B (dead after MMA -> overlay)
#define SZ_H   73728             // z_hi bf16 [128][72]
#define SZ_L   92160             // z_lo
#define SEN    110592            // float[512]
#define SZSQP  112640            // float[512]
#define SZSQ   114688            // float[128]
#define S_WS   115200            // double[16]
#define S_WS2  115328            // double[16]
#define MAIN_SMEM 115456
// ---- overlays inside SE_H (valid only AFTER post-MMA syncthreads) ----
#define OV_BEST  0               // float[256]
#define OV_SEC   1024            // float[256]
#define OV_KID   2048            // int[256]
#define OV_HIST  3072            // int[512]
#define OV_ROWK  5120            // int[128]
#define OV_FBC   5632            // int
#define OV_FBR   5760            // int[128]
#define OV_FBK2  6272            // int[16]
#define OV_FBS2  6336            // float[16]
#define OV_FBK   6400            // int[8]
#define OV_FBSC  6432            // float[8]
#define OV_LAST  6464            // int
#define OV_FZS   8192            // float[8][64]
#define OV_FZQ   10240           // float[8]
#define OV_FSC   16384           // float[8][512]

// ===========================================================================
// Prep: codebook -> bf16 hi of -2e at pitch 72 (global) + eN
// ===========================================================================
__global__ void prep_kernel(const float* __restrict__ e) {
    int t = blockIdx.x * blockDim.x + threadIdx.x;   // 64 x 512 = 32768
    int k = t >> 6, d = t & 63;
    float m = -2.f * e[t];
    ((__nv_bfloat16*)g_ebh4)[k * 72 + d] = __float2bfloat16_rn(m);
    if (blockIdx.x == 0) {
        const float4* row = (const float4*)(e + threadIdx.x * DDIM);
        float s = 0.f;
        #pragma unroll
        for (int q = 0; q < 16; ++q) {
            float4 w = __ldg(row + q);
            s = fmaf(w.x, w.x, s); s = fmaf(w.y, w.y, s);
            s = fmaf(w.z, w.z, s); s = fmaf(w.w, w.w, s);
        }
        g_en[threadIdx.x] = s;
    }
}

// ===========================================================================
// Main: 2-pass bf16 MMA filter (zh*eh + zl*eh) + margin + in-CTA exact
// fallback + fused last-CTA finalize.  2 CTAs/SM target.
// ===========================================================================
__global__ __launch_bounds__(NTHR, 2)
void vq_mma_kernel(const float* __restrict__ z, const float* __restrict__ e,
                   float* __restrict__ out, int out_size) {
    extern __shared__ char sm[];
    __nv_bfloat16* sZh = (__nv_bfloat16*)(sm + SZ_H);
    __nv_bfloat16* sZl = (__nv_bfloat16*)(sm + SZ_L);
    float*  sEN   = (float*)(sm + SEN);
    float*  sZsqP = (float*)(sm + SZSQP);
    float*  sZsq  = (float*)(sm + SZSQ);
    double* sW    = (double*)(sm + S_WS);
    double* sW2   = (double*)(sm + S_WS2);
    // overlays (post-MMA only)
    float*  sBest = (float*)(sm + OV_BEST);
    float*  sSec  = (float*)(sm + OV_SEC);
    int*    sK    = (int*)(sm + OV_KID);
    int*    sHist = (int*)(sm + OV_HIST);
    int*    sRowK = (int*)(sm + OV_ROWK);
    int*    sFbC  = (int*)(sm + OV_FBC);
    int*    sFbR  = (int*)(sm + OV_FBR);
    int*    sFbK2 = (int*)(sm + OV_FBK2);
    float*  sFbS2 = (float*)(sm + OV_FBS2);
    int*    sFbK  = (int*)(sm + OV_FBK);
    float*  sFbSC = (float*)(sm + OV_FBSC);
    int*    sLast = (int*)(sm + OV_LAST);

    const int tid  = threadIdx.x;
    const int lane = tid & 31;
    const int w    = tid >> 5;
    const int p0   = blockIdx.x * 128;
    const int zbase = (p0 >> 12) * 262144 + (p0 & 4095);

    // ---- stage codebook hi (wide copy) + eN ----
    {
        uint4* dEh = (uint4*)(sm + SE_H);
        #pragma unroll
        for (int i = 0; i < 9; ++i) {              // 4608 = 512*9
            int idx = tid + NTHR * i;
            dEh[idx] = g_ebh4[idx];
        }
        sEN[tid] = g_en[tid];
    }
    // ---- stage z: bf16 hi/lo + zsq partials (validated) ----
    {
        const int row  = tid & 127;
        const int part = tid >> 7;
        float s = 0.f;
        #pragma unroll
        for (int j = 0; j < 16; ++j) {
            int d = part * 16 + j;
            float v = __ldg(z + zbase + row + d * 4096);
            s = fmaf(v, v, s);
            __nv_bfloat16 h = __float2bfloat16_rn(v);
            __nv_bfloat16 l = __float2bfloat16_rn(v - __bfloat162float(h));
            sZh[row * 72 + d] = h;
            sZl[row * 72 + d] = l;
        }
        sZsqP[part * 128 + row] = s;
    }
    __syncthreads();
    if (tid < 128)
        sZsq[tid] = ((sZsqP[tid] + sZsqP[128 + tid]) + sZsqP[256 + tid]) + sZsqP[384 + tid];
    __syncthreads();

    // ---- MMA streaming: warp = (m-tile, code-half); 2 n-tiles per iter ----
    const int mtile = w & 7;
    const int nhalf = w >> 3;
    const int m0  = mtile * 16;
    const int g   = lane >> 2;
    const int tig = lane & 3;

    const unsigned smemBase = smem_u32(sm);
    // A ldmatrix lane addr: row-half = bit3 of lane, k-half = bit4
    const unsigned aRow = (unsigned)((m0 + ((lane >> 3) & 1) * 8 + (lane & 7)) * 144
                                     + (lane >> 4) * 16);
    const unsigned aAh = smemBase + SZ_H + aRow;
    const unsigned aAl = smemBase + SZ_L + aRow;
    // B ldmatrix lane addr: tile = bit4, k-half = bit3
    const int nbase0 = nhalf * 256;
    const unsigned bConst = smemBase + SE_H
        + (unsigned)(((lane >> 4) * 8 + (lane & 7)) * 144 + ((lane >> 3) & 1) * 16)
        + (unsigned)nbase0 * 144u;

    unsigned Ah[4][4];                  // resident A-hi (16 regs)
    #pragma unroll
    for (int ks = 0; ks < 4; ++ks)
        LDSM4(Ah[ks][0], Ah[ks][1], Ah[ks][2], Ah[ks][3], aAh + ks * 32u);

    const float zq0 = sZsq[m0 + g];
    const float zq1 = sZsq[m0 + g + 8];

    float best0 = 3.4e38f, sec0 = 3.4e38f, best1 = 3.4e38f, sec1 = 3.4e38f;
    int k0 = 0, k1 = 0;

    for (int nt2 = 0; nt2 < 16; ++nt2) {
        const int nb = nbase0 + nt2 * 16;
        float c[2][4];
        c[0][0] = c[0][1] = c[0][2] = c[0][3] = 0.f;
        c[1][0] = c[1][1] = c[1][2] = c[1][3] = 0.f;
        #pragma unroll
        for (int ks = 0; ks < 4; ++ks) {
            unsigned b0, b1, b2, b3, l0, l1, l2, l3;
            LDSM4(b0, b1, b2, b3, bConst + (unsigned)(nt2 * 2304 + ks * 32));
            LDSM4(l0, l1, l2, l3, aAl + ks * 32u);
            mma16816(c[0][0], c[0][1], c[0][2], c[0][3],
                     Ah[ks][0], Ah[ks][1], Ah[ks][2], Ah[ks][3], b0, b1);   // zh*eh t0
            mma16816(c[1][0], c[1][1], c[1][2], c[1][3],
                     Ah[ks][0], Ah[ks][1], Ah[ks][2], Ah[ks][3], b2, b3);   // zh*eh t1
            mma16816(c[0][0], c[0][1], c[0][2], c[0][3], l0, l1, l2, l3, b0, b1); // zl*eh t0
            mma16816(c[1][0], c[1][1], c[1][2], c[1][3], l0, l1, l2, l3, b2, b3); // zl*eh t1
        }
        #pragma unroll
        for (int t = 0; t < 2; ++t) {
            const int kA = nb + t * 8 + 2 * tig;
            const float2 en = *(const float2*)&sEN[kA];
            float s00 = (zq0 + en.x) + c[t][0];
            float s01 = (zq0 + en.y) + c[t][1];
            float s10 = (zq1 + en.x) + c[t][2];
            float s11 = (zq1 + en.y) + c[t][3];
            if (s00 < best0) { sec0 = best0; best0 = s00; k0 = kA; } else if (s00 < sec0) sec0 = s00;
            if (s01 < best0) { sec0 = best0; best0 = s01; k0 = kA + 1; } else if (s01 < sec0) sec0 = s01;
            if (s10 < best1) { sec1 = best1; best1 = s10; k1 = kA; } else if (s10 < sec1) sec1 = s10;
            if (s11 < best1) { sec1 = best1; best1 = s11; k1 = kA + 1; } else if (s11 < sec1) sec1 = s11;
        }
    }

    // cross-lane merge within 4-lane groups (validated)
    #pragma unroll
    for (int d = 1; d <= 2; d <<= 1) {
        float ob = __shfl_xor_sync(0xffffffffu, best0, d);
        int   ok = __shfl_xor_sync(0xffffffffu, k0, d);
        float os = __shfl_xor_sync(0xffffffffu, sec0, d);
        float worse = fmaxf(best0, ob);
        float news  = fminf(worse, fminf(sec0, os));
        bool take = (ob < best0) || (ob == best0 && ok < k0);
        best0 = take ? ob : best0; k0 = take ? ok : k0; sec0 = news;

        ob = __shfl_xor_sync(0xffffffffu, best1, d);
        ok = __shfl_xor_sync(0xffffffffu, k1, d);
        os = __shfl_xor_sync(0xffffffffu, sec1, d);
        worse = fmaxf(best1, ob);
        news  = fminf(worse, fminf(sec1, os));
        take = (ob < best1) || (ob == best1 && ok < k1);
        best1 = take ? ob : best1; k1 = take ? ok : k1; sec1 = news;
    }

    // ---- ALL warps done reading E_H before overlay writes ----
    __syncthreads();
    if (tig == 0) {
        int r0 = m0 + g, r1 = m0 + g + 8;
        sBest[r0 * 2 + nhalf] = best0; sK[r0 * 2 + nhalf] = k0; sSec[r0 * 2 + nhalf] = sec0;
        sBest[r1 * 2 + nhalf] = best1; sK[r1 * 2 + nhalf] = k1; sSec[r1 * 2 + nhalf] = sec1;
    }
    sHist[tid] = 0;
    if (tid == 0) *sFbC = 0;
    __syncthreads();

    // ---- per-row merge + margin test -> sRowK ----
    double dacc = 0.0;
    if (tid < 128) {
        const int row = tid;
        float b0 = sBest[row * 2],     s0 = sSec[row * 2];     int kk0 = sK[row * 2];
        float b1 = sBest[row * 2 + 1], s1 = sSec[row * 2 + 1]; int kk1 = sK[row * 2 + 1];
        bool take1 = (b1 < b0);
        float bb = take1 ? b1 : b0;
        int   kk = take1 ? kk1 : kk0;
        float ss = fminf(fmaxf(b0, b1), fminf(s0, s1));
        if (ss - bb > TAU) {
            atomicAdd(&sHist[kk], 1);
            dacc = (double)bb;
            sRowK[row] = kk;
        } else {
            int idx = atomicAdd(sFbC, 1);
            sFbR[idx] = row;
            sRowK[row] = -1;
        }
    }
    __syncthreads();

    // ---- z_q scatter: all 512 threads, coalesced ----
    {
        const int r = tid & 127, part = tid >> 7;
        const int kk = sRowK[r];
        if (kk >= 0) {
            const float4* er = (const float4*)(e + kk * DDIM) + part * 4;
            float* o = out + 1 + zbase + r;
            #pragma unroll
            for (int q = 0; q < 4; ++q) {
                float4 v = __ldg(er + q);
                int d0 = part * 16 + 4 * q;
                o[(d0)     * 4096] = v.x;
                o[(d0 + 1) * 4096] = v.y;
                o[(d0 + 2) * 4096] = v.z;
                o[(d0 + 3) * 4096] = v.w;
            }
        }
    }
    __syncthreads();

    // ---- in-CTA exact fp32 fallback (validated R8-R10 code, overlay buffers) ----
    const int nfb = *sFbC;
    double fbacc = 0.0;
    float* fsc = (float*)(sm + OV_FSC);
    float* fzs = (float*)(sm + OV_FZS);
    float* fzq = (float*)(sm + OV_FZQ);
    for (int base = 0; base < nfb; base += 8) {
        const int nb = min(8, nfb - base);
        {
            int r = tid >> 6, d = tid & 63;
            if (r < nb)
                fzs[r * 64 + d] = __ldg(z + zbase + sFbR[base + r] + d * 4096);
        }
        __syncthreads();
        if (tid < nb) {
            float s = 0.f;
            #pragma unroll 8
            for (int d = 0; d < 64; ++d) { float f = fzs[tid * 64 + d]; s = fmaf(f, f, s); }
            fzq[tid] = s;
        }
        __syncthreads();
        {
            float alo[8], ahi[8], blo[8], bhi[8];
            #pragma unroll
            for (int r = 0; r < 8; ++r) { alo[r] = ahi[r] = blo[r] = bhi[r] = 0.f; }
            float s_en = 0.f;
            const float4* er = (const float4*)(e + tid * DDIM);
            #pragma unroll
            for (int q = 0; q < 16; ++q) {
                float4 v = __ldg(er + q);
                s_en = fmaf(v.x, v.x, s_en); s_en = fmaf(v.y, v.y, s_en);
                s_en = fmaf(v.z, v.z, s_en); s_en = fmaf(v.w, v.w, s_en);
                float mx = -2.f * v.x, my = -2.f * v.y, mz = -2.f * v.z, mw = -2.f * v.w;
                #pragma unroll
                for (int r = 0; r < 8; ++r) {
                    float4 zv = *(const float4*)&fzs[r * 64 + 4 * q];
                    alo[r] = fmaf(zv.x, mx, alo[r]);
                    ahi[r] = fmaf(zv.y, my, ahi[r]);
                    blo[r] = fmaf(zv.z, mz, blo[r]);
                    bhi[r] = fmaf(zv.w, mw, bhi[r]);
                }
            }
            #pragma unroll
            for (int r = 0; r < 8; ++r) {
                float s = (alo[r] + blo[r]) + (ahi[r] + bhi[r]);
                fsc[r * 512 + tid] = (fzq[r] + s_en) + s;
            }
        }
        __syncthreads();
        {
            int r = tid >> 6, j = tid & 63;
            float bs = 3.4e38f; int bk = 1 << 30;
            if (r < nb) {
                #pragma unroll
                for (int i = 0; i < 8; ++i) {
                    int k = j + 64 * i;
                    float s = fsc[r * 512 + k];
                    if (s < bs || (s == bs && k < bk)) { bs = s; bk = k; }
                }
            }
            #pragma unroll
            for (int off = 16; off > 0; off >>= 1) {
                float os = __shfl_down_sync(0xffffffffu, bs, off);
                int   ok = __shfl_down_sync(0xffffffffu, bk, off);
                if (os < bs || (os == bs && ok < bk)) { bs = os; bk = ok; }
            }
            if (lane == 0 && r < nb) {
                int half = (tid >> 5) & 1;
                sFbK2[r * 2 + half] = bk;
                sFbS2[r * 2 + half] = bs;
            }
        }
        __syncthreads();
        if (tid < nb) {
            int kk0 = sFbK2[tid * 2], kk1 = sFbK2[tid * 2 + 1];
            float s0 = sFbS2[tid * 2], s1 = sFbS2[tid * 2 + 1];
            bool t1 = (s1 < s0) || (s1 == s0 && kk1 < kk0);
            int kk = t1 ? kk1 : kk0;
            sFbK[tid]  = kk;
            sFbSC[tid] = t1 ? s1 : s0;
            atomicAdd(&sHist[kk], 1);
        }
        __syncthreads();
        if (tid == 0) {
            for (int r = 0; r < nb; ++r) fbacc += (double)sFbSC[r];
        }
        if (tid < 128) {
            int r = tid >> 4, q = tid & 15;
            if (r < nb) {
                int kk = sFbK[r];
                float4 v = __ldg((const float4*)(e + kk * DDIM) + q);
                float* o = out + 1 + zbase + sFbR[base + r];
                o[(4 * q)     * 4096] = v.x;
                o[(4 * q + 1) * 4096] = v.y;
                o[(4 * q + 2) * 4096] = v.z;
                o[(4 * q + 3) * 4096] = v.w;
            }
        }
        __syncthreads();
    }

    // ---- per-CTA reductions out ----
    #pragma unroll
    for (int off = 16; off > 0; off >>= 1)
        dacc += __shfl_down_sync(0xffffffffu, dacc, off);
    if (tid < 128 && lane == 0) sW[w] = dacc;
    __syncthreads();
    if (tid == 0)
        g_sse[blockIdx.x] = ((((sW[0] + sW[1]) + sW[2]) + sW[3])) + fbacc;
    {
        int c = sHist[tid];
        if (c) atomicAdd(&g_counts[tid], c);
    }

    // ---- fused finalize: last CTA does loss + perplexity ----
    __threadfence();
    __syncthreads();
    if (tid == 0) *sLast = (atomicAdd(&g_done, 1u) == GRID - 1u) ? 1 : 0;
    __syncthreads();
    if (*sLast) {
        __threadfence();
        double em = (double)g_counts[tid] * (1.0 / 131072.0);
        g_counts[tid] = 0;
        double x = em + 1e-10;
        double term = x * log(x);
        double ds = g_sse[tid] + g_sse[tid + 512];
        #pragma unroll
        for (int off = 16; off > 0; off >>= 1) {
            term += __shfl_down_sync(0xffffffffu, term, off);
            ds   += __shfl_down_sync(0xffffffffu, ds, off);
        }
        if (lane == 0) { sW[w] = ds; sW2[w] = term; }
        __syncthreads();
        if (tid == 0) {
            double ent = 0.0, sse = 0.0;
            #pragma unroll
            for (int i = 0; i < 16; ++i) { ent += sW2[i]; sse += sW[i]; }
            double mse = sse / 8388608.0;
            out[0]            = (float)(1.25 * mse);
            out[out_size - 1] = (float)exp(-ent);
            g_done = 0;                       // replay-safe reset
        }
    }
}

// ---------------------------------------------------------------------------
extern "C" void kernel_launch(void* const* d_in, const int* in_sizes, int n_in,
                              void* d_out, int out_size) {
    const float* z = (const float*)d_in[0];
    const float* e = (const float*)d_in[1];
    if (n_in >= 2 && in_sizes[0] == KCODES * DDIM && in_sizes[1] == N_POS * DDIM) {
        const float* tmp = z; z = e; e = tmp;      // defensive order swap
    }
    cudaFuncSetAttribute(vq_mma_kernel, cudaFuncAttributeMaxDynamicSharedMemorySize, MAIN_SMEM);

    prep_kernel<<<64, 512>>>(e);
    vq_mma_kernel<<<GRID, NTHR, MAIN_SMEM>>>(z, e, (float*)d_out, out_size);
}

// round 13
// speedup vs baseline: 8.5797x; 1.1812x over previous
#include <cuda_runtime.h>
#include <cuda_fp16.h>
#include <math.h>

#define N_POS   131072
#define KCODES  512
#define DDIM    64
#define GRID    1024             // 128 positions per CTA
#define NTHR    512
#define TAU     2e-4f

// ---- device scratch (no allocation allowed) ----
__device__ uint4  g_ef16[4608];    // fp16 of -2e, [k][pitch72 halves]  (73728 B)
__device__ float  g_en[KCODES];
__device__ int    g_counts[KCODES];
__device__ double g_sse[GRID];
__device__ unsigned g_done;        // zero-init; self-resetting

// ---------- helpers ----------
static __device__ __forceinline__ void mma16816h(float& c0, float& c1, float& c2, float& c3,
                                                 unsigned a0, unsigned a1, unsigned a2, unsigned a3,
                                                 unsigned b0, unsigned b1) {
    asm volatile("mma.sync.aligned.m16n8k16.row.col.f32.f16.f16.f32 "
                 "{%0,%1,%2,%3}, {%4,%5,%6,%7}, {%8,%9}, {%0,%1,%2,%3};"
                 : "+f"(c0), "+f"(c1), "+f"(c2), "+f"(c3)
                 : "r"(a0), "r"(a1), "r"(a2), "r"(a3), "r"(b0), "r"(b1));
}
#define LDSM4(d0, d1, d2, d3, addr)                                          \
    asm volatile("ldmatrix.sync.aligned.m8n8.x4.shared.b16 {%0,%1,%2,%3}, [%4];" \
                 : "=r"(d0), "=r"(d1), "=r"(d2), "=r"(d3) : "r"(addr))

static __device__ __forceinline__ unsigned smem_u32(const void* p) {
    unsigned a;
    asm("{ .reg .u64 t; cvta.to.shared.u64 t, %1; cvt.u32.u64 %0, t; }" : "=r"(a) : "l"(p));
    return a;
}

// ---------- smem layout (bytes), fixed regions: 97024 total ----------
#define SE_H   0                 // e fp16 [512][72] pitch 144B (dead after MMA -> overlay)
#define SZ_H   73728             // z fp16 [128][72]
#define SEN    92160             // float[512]
#define SZSQP  94208             // float[512]
#define SZSQ   96256             // float[128]
#define S_WS   96768             // double[16]
#define S_WS2  96896             // double[16]
#define MAIN_SMEM 97024
// ---- overlays inside SE_H (valid only AFTER post-MMA syncthreads) ----
#define OV_BEST  0               // float[256]
#define OV_SEC   1024            // float[256]
#define OV_KID   2048            // int[256]
#define OV_HIST  3072            // int[512]
#define OV_ROWK  5120            // int[128]
#define OV_FBC   5632            // int
#define OV_FBR   5760            // int[128]
#define OV_FBK2  6272            // int[16]
#define OV_FBS2  6336            // float[16]
#define OV_FBK   6400            // int[8]
#define OV_FBSC  6432            // float[8]
#define OV_LAST  6464            // int
#define OV_FZS   8192            // float[8][64]
#define OV_FZQ   10240           // float[8]
#define OV_FSC   16384           // float[8][512]

// ===========================================================================
// Prep: codebook -> fp16 of -2e at pitch 72 (global) + eN
// ===========================================================================
__global__ void prep_kernel(const float* __restrict__ e) {
    int t = blockIdx.x * blockDim.x + threadIdx.x;   // 64 x 512 = 32768
    int k = t >> 6, d = t & 63;
    ((__half*)g_ef16)[k * 72 + d] = __float2half_rn(-2.f * e[t]);
    if (blockIdx.x == 0) {
        const float4* row = (const float4*)(e + threadIdx.x * DDIM);
        float s = 0.f;
        #pragma unroll
        for (int q = 0; q < 16; ++q) {
            float4 w = __ldg(row + q);
            s = fmaf(w.x, w.x, s); s = fmaf(w.y, w.y, s);
            s = fmaf(w.z, w.z, s); s = fmaf(w.w, w.w, s);
        }
        g_en[threadIdx.x] = s;
    }
}

// ===========================================================================
// Main: single-pass fp16 MMA filter + margin + in-CTA exact fallback +
// fused last-CTA finalize.  2 CTAs/SM.
// ===========================================================================
__global__ __launch_bounds__(NTHR, 2)
void vq_mma_kernel(const float* __restrict__ z, const float* __restrict__ e,
                   float* __restrict__ out, int out_size) {
    extern __shared__ char sm[];
    __half* sZh = (__half*)(sm + SZ_H);
    float*  sEN   = (float*)(sm + SEN);
    float*  sZsqP = (float*)(sm + SZSQP);
    float*  sZsq  = (float*)(sm + SZSQ);
    double* sW    = (double*)(sm + S_WS);
    double* sW2   = (double*)(sm + S_WS2);
    // overlays (post-MMA only)
    float*  sBest = (float*)(sm + OV_BEST);
    float*  sSec  = (float*)(sm + OV_SEC);
    int*    sK    = (int*)(sm + OV_KID);
    int*    sHist = (int*)(sm + OV_HIST);
    int*    sRowK = (int*)(sm + OV_ROWK);
    int*    sFbC  = (int*)(sm + OV_FBC);
    int*    sFbR  = (int*)(sm + OV_FBR);
    int*    sFbK2 = (int*)(sm + OV_FBK2);
    float*  sFbS2 = (float*)(sm + OV_FBS2);
    int*    sFbK  = (int*)(sm + OV_FBK);
    float*  sFbSC = (float*)(sm + OV_FBSC);
    int*    sLast = (int*)(sm + OV_LAST);

    const int tid  = threadIdx.x;
    const int lane = tid & 31;
    const int w    = tid >> 5;
    const int p0   = blockIdx.x * 128;
    const int zbase = (p0 >> 12) * 262144 + (p0 & 4095);

    // ---- stage codebook fp16 (wide copy) + eN ----
    {
        uint4* dEh = (uint4*)(sm + SE_H);
        #pragma unroll
        for (int i = 0; i < 9; ++i) {              // 4608 = 512*9
            int idx = tid + NTHR * i;
            dEh[idx] = g_ef16[idx];
        }
        sEN[tid] = g_en[tid];
    }
    // ---- stage z: fp16 + zsq partials ----
    {
        const int row  = tid & 127;
        const int part = tid >> 7;
        float s = 0.f;
        #pragma unroll
        for (int j = 0; j < 16; ++j) {
            int d = part * 16 + j;
            float v = __ldg(z + zbase + row + d * 4096);
            s = fmaf(v, v, s);
            sZh[row * 72 + d] = __float2half_rn(v);
        }
        sZsqP[part * 128 + row] = s;
    }
    __syncthreads();
    if (tid < 128)
        sZsq[tid] = ((sZsqP[tid] + sZsqP[128 + tid]) + sZsqP[256 + tid]) + sZsqP[384 + tid];
    __syncthreads();

    // ---- MMA streaming: warp = (m-tile, code-half); 2 n-tiles per iter ----
    const int mtile = w & 7;
    const int nhalf = w >> 3;
    const int m0  = mtile * 16;
    const int g   = lane >> 2;
    const int tig = lane & 3;

    const unsigned smemBase = smem_u32(sm);
    // A ldmatrix lane addr: row-half = bit3 of lane, k-half = bit4
    const unsigned aRow = (unsigned)((m0 + ((lane >> 3) & 1) * 8 + (lane & 7)) * 144
                                     + (lane >> 4) * 16);
    const unsigned aAh = smemBase + SZ_H + aRow;
    // B ldmatrix lane addr: tile = bit4, k-half = bit3
    const int nbase0 = nhalf * 256;
    const unsigned bConst = smemBase + SE_H
        + (unsigned)(((lane >> 4) * 8 + (lane & 7)) * 144 + ((lane >> 3) & 1) * 16)
        + (unsigned)nbase0 * 144u;

    unsigned Ah[4][4];                  // resident A (16 regs)
    #pragma unroll
    for (int ks = 0; ks < 4; ++ks)
        LDSM4(Ah[ks][0], Ah[ks][1], Ah[ks][2], Ah[ks][3], aAh + ks * 32u);

    const float zq0 = sZsq[m0 + g];
    const float zq1 = sZsq[m0 + g + 8];

    float best0 = 3.4e38f, sec0 = 3.4e38f, best1 = 3.4e38f, sec1 = 3.4e38f;
    int k0 = 0, k1 = 0;

    for (int nt2 = 0; nt2 < 16; ++nt2) {
        const int nb = nbase0 + nt2 * 16;
        float c[2][4];
        c[0][0] = c[0][1] = c[0][2] = c[0][3] = 0.f;
        c[1][0] = c[1][1] = c[1][2] = c[1][3] = 0.f;
        #pragma unroll
        for (int ks = 0; ks < 4; ++ks) {
            unsigned b0, b1, b2, b3;
            LDSM4(b0, b1, b2, b3, bConst + (unsigned)(nt2 * 2304 + ks * 32));
            mma16816h(c[0][0], c[0][1], c[0][2], c[0][3],
                      Ah[ks][0], Ah[ks][1], Ah[ks][2], Ah[ks][3], b0, b1);   // tile 0
            mma16816h(c[1][0], c[1][1], c[1][2], c[1][3],
                      Ah[ks][0], Ah[ks][1], Ah[ks][2], Ah[ks][3], b2, b3);   // tile 1
        }
        #pragma unroll
        for (int t = 0; t < 2; ++t) {
            const int kA = nb + t * 8 + 2 * tig;
            const float2 en = *(const float2*)&sEN[kA];
            float s00 = (zq0 + en.x) + c[t][0];
            float s01 = (zq0 + en.y) + c[t][1];
            float s10 = (zq1 + en.x) + c[t][2];
            float s11 = (zq1 + en.y) + c[t][3];
            if (s00 < best0) { sec0 = best0; best0 = s00; k0 = kA; } else if (s00 < sec0) sec0 = s00;
            if (s01 < best0) { sec0 = best0; best0 = s01; k0 = kA + 1; } else if (s01 < sec0) sec0 = s01;
            if (s10 < best1) { sec1 = best1; best1 = s10; k1 = kA; } else if (s10 < sec1) sec1 = s10;
            if (s11 < best1) { sec1 = best1; best1 = s11; k1 = kA + 1; } else if (s11 < sec1) sec1 = s11;
        }
    }

    // cross-lane merge within 4-lane groups (validated)
    #pragma unroll
    for (int d = 1; d <= 2; d <<= 1) {
        float ob = __shfl_xor_sync(0xffffffffu, best0, d);
        int   ok = __shfl_xor_sync(0xffffffffu, k0, d);
        float os = __shfl_xor_sync(0xffffffffu, sec0, d);
        float worse = fmaxf(best0, ob);
        float news  = fminf(worse, fminf(sec0, os));
        bool take = (ob < best0) || (ob == best0 && ok < k0);
        best0 = take ? ob : best0; k0 = take ? ok : k0; sec0 = news;

        ob = __shfl_xor_sync(0xffffffffu, best1, d);
        ok = __shfl_xor_sync(0xffffffffu, k1, d);
        os = __shfl_xor_sync(0xffffffffu, sec1, d);
        worse = fmaxf(best1, ob);
        news  = fminf(worse, fminf(sec1, os));
        take = (ob < best1) || (ob == best1 && ok < k1);
        best1 = take ? ob : best1; k1 = take ? ok : k1; sec1 = news;
    }

    // ---- ALL warps done reading E before overlay writes ----
    __syncthreads();
    if (tig == 0) {
        int r0 = m0 + g, r1 = m0 + g + 8;
        sBest[r0 * 2 + nhalf] = best0; sK[r0 * 2 + nhalf] = k0; sSec[r0 * 2 + nhalf] = sec0;
        sBest[r1 * 2 + nhalf] = best1; sK[r1 * 2 + nhalf] = k1; sSec[r1 * 2 + nhalf] = sec1;
    }
    sHist[tid] = 0;
    if (tid == 0) *sFbC = 0;
    __syncthreads();

    // ---- per-row merge + margin test -> sRowK ----
    double dacc = 0.0;
    if (tid < 128) {
        const int row = tid;
        float b0 = sBest[row * 2],     s0 = sSec[row * 2];     int kk0 = sK[row * 2];
        float b1 = sBest[row * 2 + 1], s1 = sSec[row * 2 + 1]; int kk1 = sK[row * 2 + 1];
        bool take1 = (b1 < b0);
        float bb = take1 ? b1 : b0;
        int   kk = take1 ? kk1 : kk0;
        float ss = fminf(fmaxf(b0, b1), fminf(s0, s1));
        if (ss - bb > TAU) {
            atomicAdd(&sHist[kk], 1);
            dacc = (double)bb;
            sRowK[row] = kk;
        } else {
            int idx = atomicAdd(sFbC, 1);
            sFbR[idx] = row;
            sRowK[row] = -1;
        }
    }
    __syncthreads();

    // ---- z_q scatter: all 512 threads, coalesced ----
    {
        const int r = tid & 127, part = tid >> 7;
        const int kk = sRowK[r];
        if (kk >= 0) {
            const float4* er = (const float4*)(e + kk * DDIM) + part * 4;
            float* o = out + 1 + zbase + r;
            #pragma unroll
            for (int q = 0; q < 4; ++q) {
                float4 v = __ldg(er + q);
                int d0 = part * 16 + 4 * q;
                o[(d0)     * 4096] = v.x;
                o[(d0 + 1) * 4096] = v.y;
                o[(d0 + 2) * 4096] = v.z;
                o[(d0 + 3) * 4096] = v.w;
            }
        }
    }
    __syncthreads();

    // ---- in-CTA exact fp32 fallback (validated R8-R11 code, overlay buffers) ----
    const int nfb = *sFbC;
    double fbacc = 0.0;
    float* fsc = (float*)(sm + OV_FSC);
    float* fzs = (float*)(sm + OV_FZS);
    float* fzq = (float*)(sm + OV_FZQ);
    for (int base = 0; base < nfb; base += 8) {
        const int nb = min(8, nfb - base);
        {
            int r = tid >> 6, d = tid & 63;
            if (r < nb)
                fzs[r * 64 + d] = __ldg(z + zbase + sFbR[base + r] + d * 4096);
        }
        __syncthreads();
        if (tid < nb) {
            float s = 0.f;
            #pragma unroll 8
            for (int d = 0; d < 64; ++d) { float f = fzs[tid * 64 + d]; s = fmaf(f, f, s); }
            fzq[tid] = s;
        }
        __syncthreads();
        {
            float alo[8], ahi[8], blo[8], bhi[8];
            #pragma unroll
            for (int r = 0; r < 8; ++r) { alo[r] = ahi[r] = blo[r] = bhi[r] = 0.f; }
            float s_en = 0.f;
            const float4* er = (const float4*)(e + tid * DDIM);
            #pragma unroll
            for (int q = 0; q < 16; ++q) {
                float4 v = __ldg(er + q);
                s_en = fmaf(v.x, v.x, s_en); s_en = fmaf(v.y, v.y, s_en);
                s_en = fmaf(v.z, v.z, s_en); s_en = fmaf(v.w, v.w, s_en);
                float mx = -2.f * v.x, my = -2.f * v.y, mz = -2.f * v.z, mw = -2.f * v.w;
                #pragma unroll
                for (int r = 0; r < 8; ++r) {
                    float4 zv = *(const float4*)&fzs[r * 64 + 4 * q];
                    alo[r] = fmaf(zv.x, mx, alo[r]);
                    ahi[r] = fmaf(zv.y, my, ahi[r]);
                    blo[r] = fmaf(zv.z, mz, blo[r]);
                    bhi[r] = fmaf(zv.w, mw, bhi[r]);
                }
            }
            #pragma unroll
            for (int r = 0; r < 8; ++r) {
                float s = (alo[r] + blo[r]) + (ahi[r] + bhi[r]);
                fsc[r * 512 + tid] = (fzq[r] + s_en) + s;
            }
        }
        __syncthreads();
        {
            int r = tid >> 6, j = tid & 63;
            float bs = 3.4e38f; int bk = 1 << 30;
            if (r < nb) {
                #pragma unroll
                for (int i = 0; i < 8; ++i) {
                    int k = j + 64 * i;
                    float s = fsc[r * 512 + k];
                    if (s < bs || (s == bs && k < bk)) { bs = s; bk = k; }
                }
            }
            #pragma unroll
            for (int off = 16; off > 0; off >>= 1) {
                float os = __shfl_down_sync(0xffffffffu, bs, off);
                int   ok = __shfl_down_sync(0xffffffffu, bk, off);
                if (os < bs || (os == bs && ok < bk)) { bs = os; bk = ok; }
            }
            if (lane == 0 && r < nb) {
                int half = (tid >> 5) & 1;
                sFbK2[r * 2 + half] = bk;
                sFbS2[r * 2 + half] = bs;
            }
        }
        __syncthreads();
        if (tid < nb) {
            int kk0 = sFbK2[tid * 2], kk1 = sFbK2[tid * 2 + 1];
            float s0 = sFbS2[tid * 2], s1 = sFbS2[tid * 2 + 1];
            bool t1 = (s1 < s0) || (s1 == s0 && kk1 < kk0);
            int kk = t1 ? kk1 : kk0;
            sFbK[tid]  = kk;
            sFbSC[tid] = t1 ? s1 : s0;
            atomicAdd(&sHist[kk], 1);
        }
        __syncthreads();
        if (tid == 0) {
            for (int r = 0; r < nb; ++r) fbacc += (double)sFbSC[r];
        }
        if (tid < 128) {
            int r = tid >> 4, q = tid & 15;
            if (r < nb) {
                int kk = sFbK[r];
                float4 v = __ldg((const float4*)(e + kk * DDIM) + q);
                float* o = out + 1 + zbase + sFbR[base + r];
                o[(4 * q)     * 4096] = v.x;
                o[(4 * q + 1) * 4096] = v.y;
                o[(4 * q + 2) * 4096] = v.z;
                o[(4 * q + 3) * 4096] = v.w;
            }
        }
        __syncthreads();
    }

    // ---- per-CTA reductions out ----
    #pragma unroll
    for (int off = 16; off > 0; off >>= 1)
        dacc += __shfl_down_sync(0xffffffffu, dacc, off);
    if (tid < 128 && lane == 0) sW[w] = dacc;
    __syncthreads();
    if (tid == 0)
        g_sse[blockIdx.x] = ((((sW[0] + sW[1]) + sW[2]) + sW[3])) + fbacc;
    {
        int c = sHist[tid];
        if (c) atomicAdd(&g_counts[tid], c);
    }

    // ---- fused finalize: last CTA does loss + perplexity ----
    __threadfence();
    __syncthreads();
    if (tid == 0) *sLast = (atomicAdd(&g_done, 1u) == GRID - 1u) ? 1 : 0;
    __syncthreads();
    if (*sLast) {
        __threadfence();
        double em = (double)g_counts[tid] * (1.0 / 131072.0);
        g_counts[tid] = 0;
        double x = em + 1e-10;
        double term = x * log(x);
        double ds = g_sse[tid] + g_sse[tid + 512];
        #pragma unroll
        for (int off = 16; off > 0; off >>= 1) {
            term += __shfl_down_sync(0xffffffffu, term, off);
            ds   += __shfl_down_sync(0xffffffffu, ds, off);
        }
        if (lane == 0) { sW[w] = ds; sW2[w] = term; }
        __syncthreads();
        if (tid == 0) {
            double ent = 0.0, sse = 0.0;
            #pragma unroll
            for (int i = 0; i < 16; ++i) { ent += sW2[i]; sse += sW[i]; }
            double mse = sse / 8388608.0;
            out[0]            = (float)(1.25 * mse);
            out[out_size - 1] = (float)exp(-ent);
            g_done = 0;                       // replay-safe reset
        }
    }
}

// ---------------------------------------------------------------------------
extern "C" void kernel_launch(void* const* d_in, const int* in_sizes, int n_in,
                              void* d_out, int out_size) {
    const float* z = (const float*)d_in[0];
    const float* e = (const float*)d_in[1];
    if (n_in >= 2 && in_sizes[0] == KCODES * DDIM && in_sizes[1] == N_POS * DDIM) {
        const float* tmp = z; z = e; e = tmp;      // defensive order swap
    }
    cudaFuncSetAttribute(vq_mma_kernel, cudaFuncAttributeMaxDynamicSharedMemorySize, MAIN_SMEM);

    prep_kernel<<<64, 512>>>(e);
    vq_mma_kernel<<<GRID, NTHR, MAIN_SMEM>>>(z, e, (float*)d_out, out_size);
}